// round 1
// baseline (speedup 1.0000x reference)
#include <cuda_runtime.h>
#include <math.h>

#define Bq   32
#define Nn   1024
#define Dd   768
#define E_TOK 4
#define E_CH  4
#define Ee    8
#define HN   4096
#define HD   3072

// 768*4096 == 1024*3072 == 3145728 — token h and channel g slots are the same size.
#define SLOT_STRIDE 3145728

#define BM 128
#define BN 128
#define BK 16
#define TM 8
#define TN 8

// Scratch: per-batch-item, per-top2-rank hidden activation slot (fp32 for accuracy).
// 64 slots * 12 MB = 805 MB. __device__ globals are the sanctioned scratch path.
__device__ float g_hidden[(size_t)Bq * 2 * SLOT_STRIDE];
__device__ float g_xmean[Bq * Dd];
__device__ float g_combine[Bq * Ee];
__device__ int   g_slot[Bq * Ee];

// ---------------------------------------------------------------- router ----

__global__ void mean_kernel(const float* __restrict__ x) {
    int b = blockIdx.x;
    const float* xb = x + (size_t)b * Nn * Dd;
    for (int d = threadIdx.x; d < Dd; d += blockDim.x) {
        float s = 0.f;
        const float* p = xb + d;
        #pragma unroll 8
        for (int n = 0; n < Nn; n++) s += p[(size_t)n * Dd];
        g_xmean[b * Dd + d] = s * (1.0f / Nn);
    }
}

__global__ void gate_kernel(const float* __restrict__ rw, float* __restrict__ aux_out) {
    __shared__ float s_probs[Bq][Ee];
    __shared__ int   s_top1[Bq];
    int warp = threadIdx.x >> 5, lane = threadIdx.x & 31;
    int nwarp = blockDim.x >> 5;
    for (int b = warp; b < Bq; b += nwarp) {
        float logits[Ee];
        #pragma unroll
        for (int e = 0; e < Ee; e++) {
            float s = 0.f;
            for (int d = lane; d < Dd; d += 32)
                s += g_xmean[b * Dd + d] * rw[e * Dd + d];
            #pragma unroll
            for (int o = 16; o; o >>= 1) s += __shfl_xor_sync(0xffffffffu, s, o);
            logits[e] = s;
        }
        if (lane == 0) {
            float mx = logits[0];
            #pragma unroll
            for (int e = 1; e < Ee; e++) mx = fmaxf(mx, logits[e]);
            float p[Ee], se = 0.f;
            #pragma unroll
            for (int e = 0; e < Ee; e++) { p[e] = expf(logits[e] - mx); se += p[e]; }
            float inv = 1.0f / se;
            #pragma unroll
            for (int e = 0; e < Ee; e++) p[e] *= inv;
            // top-2 (stable: strict > keeps lowest index on ties, matching lax.top_k)
            int i0 = 0;
            #pragma unroll
            for (int e = 1; e < Ee; e++) if (p[e] > p[i0]) i0 = e;
            int i1 = (i0 == 0) ? 1 : 0;
            #pragma unroll
            for (int e = 0; e < Ee; e++) if (e != i1 && e != i0 && p[e] > p[i1]) i1 = e;
            float ws = p[i0] + p[i1];
            #pragma unroll
            for (int e = 0; e < Ee; e++) { g_combine[b * Ee + e] = 0.f; g_slot[b * Ee + e] = -1; }
            g_combine[b * Ee + i0] = p[i0] / ws;  g_slot[b * Ee + i0] = b * 2;
            g_combine[b * Ee + i1] = p[i1] / ws;  g_slot[b * Ee + i1] = b * 2 + 1;
            #pragma unroll
            for (int e = 0; e < Ee; e++) s_probs[b][e] = p[e];
            s_top1[b] = i0;
        }
    }
    __syncthreads();
    if (threadIdx.x == 0 && aux_out != nullptr) {
        float aux = 0.f;
        for (int e = 0; e < Ee; e++) {
            float pm = 0.f; int c = 0;
            for (int b = 0; b < Bq; b++) { pm += s_probs[b][e]; c += (s_top1[b] == e); }
            aux += (pm / Bq) * ((float)c / Bq);
        }
        aux_out[0] = (float)Ee * aux;
    }
}

// ---------------------------------------------------------------- helpers ---

__device__ __forceinline__ void load_transpose(float dst[BK][BM], const float* __restrict__ src,
                                               size_t row_stride, float scale, int tid) {
    // src points at (row m0, col k0); rows are K-contiguous. 128 rows x 16 k.
    #pragma unroll
    for (int i = 0; i < 2; i++) {
        int idx = tid + i * 256;
        int m = idx >> 2, kq = idx & 3;
        float4 v = *(const float4*)(src + (size_t)m * row_stride + kq * 4);
        dst[kq * 4 + 0][m] = v.x * scale;
        dst[kq * 4 + 1][m] = v.y * scale;
        dst[kq * 4 + 2][m] = v.z * scale;
        dst[kq * 4 + 3][m] = v.w * scale;
    }
}

__device__ __forceinline__ void micro_mma(const float As[BK][BM], const float Bs[BK][BN],
                                          float acc[TM][TN], int tx, int ty) {
    #pragma unroll
    for (int k = 0; k < BK; k++) {
        float a[TM], bb[TN];
        #pragma unroll
        for (int i = 0; i < TM; i++) a[i] = As[k][ty * TM + i];
        #pragma unroll
        for (int j = 0; j < TN; j++) bb[j] = Bs[k][tx * TN + j];
        #pragma unroll
        for (int i = 0; i < TM; i++)
            #pragma unroll
            for (int j = 0; j < TN; j++)
                acc[i][j] = fmaf(a[i], bb[j], acc[i][j]);
    }
}

__device__ __forceinline__ float gelu_tanh(float v) {
    float c = 0.7978845608028654f * (v + 0.044715f * v * v * v);
    return 0.5f * v * (1.0f + tanhf(c));
}

// ---------------------------------------------------------------- GEMM1 -----
// token:   h[d,hh] = gelu( sum_n x[b,n,d] * tok_w1[e,hh,n] + b1[e,hh] )   M=768,  Nh=4096, K=1024
// channel: g[n,hh] = gelu( sum_d x[b,n,d] * ch_w1 [e,hh,d] + b1[e,hh] )   M=1024, Nh=3072, K=768

__global__ void __launch_bounds__(256) gemm1_kernel(
    const float* __restrict__ x, const float* __restrict__ w1,
    const float* __restrict__ b1, int is_token)
{
    int b  = blockIdx.z;
    int el = blockIdx.y;
    int eg = is_token ? el : (E_TOK + el);
    float w = g_combine[b * Ee + eg];
    if (w == 0.f) return;   // inactive expert for this batch item — top-2 sparsity
    int slot = g_slot[b * Ee + eg];

    int M  = is_token ? Dd : Nn;
    int Nh = is_token ? HN : HD;
    int K  = is_token ? Nn : Dd;
    (void)M;
    int tilesN = Nh / BN;
    int m0 = (blockIdx.x / tilesN) * BM;
    int n0 = (blockIdx.x % tilesN) * BN;

    __shared__ float As[BK][BM];
    __shared__ float Bs[BK][BN];
    float acc[TM][TN] = {};
    int tid = threadIdx.x, tx = tid & 15, ty = tid >> 4;

    const float* xb  = x  + (size_t)b  * Nn * Dd;
    const float* w1e = w1 + (size_t)el * Nh * K;

    for (int k0 = 0; k0 < K; k0 += BK) {
        if (is_token) {
            // A(k=n, m=d) = xb[n*Dd + d]: k-rows already m-contiguous, direct copy
            #pragma unroll
            for (int i = 0; i < 2; i++) {
                int idx = tid + i * 256;
                int k = idx >> 5, mq = idx & 31;
                *(float4*)&As[k][mq * 4] =
                    *(const float4*)(xb + (size_t)(k0 + k) * Dd + m0 + mq * 4);
            }
        } else {
            // A(m=n, k=d) = xb[n*Dd + d]: rows K-contiguous, transpose into smem
            load_transpose(As, xb + (size_t)m0 * Dd + k0, Dd, 1.0f, tid);
        }
        // B(m=hh, k): w1 rows K-contiguous, transpose
        load_transpose(Bs, w1e + (size_t)n0 * K + k0, K, 1.0f, tid);
        __syncthreads();
        micro_mma(As, Bs, acc, tx, ty);
        __syncthreads();
    }

    float* hid = g_hidden + (size_t)slot * SLOT_STRIDE;
    const float* b1e = b1 + el * Nh;
    #pragma unroll
    for (int i = 0; i < TM; i++) {
        int m = m0 + ty * TM + i;
        #pragma unroll
        for (int j = 0; j < TN; j++) {
            int h = n0 + tx * TN + j;
            hid[(size_t)m * Nh + h] = gelu_tanh(acc[i][j] + b1e[h]);
        }
    }
}

// ---------------------------------------------------------------- GEMM2 -----
// Fused second GEMM + weighted combine. One block owns a 128(n) x 128(d) output
// tile of out[b]; loops over the (<=2) active experts, accumulating
//   token e:   w * ( sum_h tok_w2[e,n,h] * hid[d,h] + tok_b2[e,n] )
//   channel e: w * ( sum_h hid[n,h] * ch_w2[e,d,h] + ch_b2[e,d] )
// The combine weight is folded into the B-tile smem load. No atomics.

__global__ void __launch_bounds__(256) gemm2_kernel(
    const float* __restrict__ tok_w2, const float* __restrict__ tok_b2,
    const float* __restrict__ ch_w2,  const float* __restrict__ ch_b2,
    float* __restrict__ out)
{
    int b = blockIdx.z;
    int tilesD = Dd / BN;   // 6
    int n0 = (blockIdx.x / tilesD) * BM;
    int d0 = (blockIdx.x % tilesD) * BN;

    __shared__ float As[BK][BM];   // n-side operand
    __shared__ float Bs[BK][BN];   // d-side operand (pre-scaled by combine weight)
    float acc[TM][TN] = {};
    int tid = threadIdx.x, tx = tid & 15, ty = tid >> 4;

    for (int eg = 0; eg < Ee; eg++) {
        float w = g_combine[b * Ee + eg];
        if (w == 0.f) continue;
        const float* hid = g_hidden + (size_t)g_slot[b * Ee + eg] * SLOT_STRIDE;

        if (eg < E_TOK) {
            int el = eg;
            const float* Ap = tok_w2 + (size_t)el * Nn * HN;  // (n, h) K-contig
            const float* Bp = hid;                            // (d, h) K-contig
            for (int k0 = 0; k0 < HN; k0 += BK) {
                load_transpose(As, Ap + (size_t)n0 * HN + k0, HN, 1.0f, tid);
                load_transpose(Bs, Bp + (size_t)d0 * HN + k0, HN, w,    tid);
                __syncthreads();
                micro_mma(As, Bs, acc, tx, ty);
                __syncthreads();
            }
            #pragma unroll
            for (int i = 0; i < TM; i++) {
                float bv = w * tok_b2[el * Nn + n0 + ty * TM + i];
                #pragma unroll
                for (int j = 0; j < TN; j++) acc[i][j] += bv;
            }
        } else {
            int el = eg - E_TOK;
            const float* Ap = hid;                            // (n, h) K-contig
            const float* Bp = ch_w2 + (size_t)el * Dd * HD;   // (d, h) K-contig
            for (int k0 = 0; k0 < HD; k0 += BK) {
                load_transpose(As, Ap + (size_t)n0 * HD + k0, HD, 1.0f, tid);
                load_transpose(Bs, Bp + (size_t)d0 * HD + k0, HD, w,    tid);
                __syncthreads();
                micro_mma(As, Bs, acc, tx, ty);
                __syncthreads();
            }
            #pragma unroll
            for (int j = 0; j < TN; j++) {
                float bv = w * ch_b2[el * Dd + d0 + tx * TN + j];
                #pragma unroll
                for (int i = 0; i < TM; i++) acc[i][j] += bv;
            }
        }
    }

    float* ob = out + (size_t)b * Nn * Dd;
    #pragma unroll
    for (int i = 0; i < TM; i++) {
        int n = n0 + ty * TM + i;
        #pragma unroll
        for (int j = 0; j < TN; j++)
            ob[(size_t)n * Dd + d0 + tx * TN + j] = acc[i][j];
    }
}

// ---------------------------------------------------------------- launch ----

extern "C" void kernel_launch(void* const* d_in, const int* in_sizes, int n_in,
                              void* d_out, int out_size) {
    const float* x      = (const float*)d_in[0];
    const float* rw     = (const float*)d_in[1];
    const float* tok_w1 = (const float*)d_in[2];
    const float* tok_b1 = (const float*)d_in[3];
    const float* tok_w2 = (const float*)d_in[4];
    const float* tok_b2 = (const float*)d_in[5];
    const float* ch_w1  = (const float*)d_in[6];
    const float* ch_b1  = (const float*)d_in[7];
    const float* ch_w2  = (const float*)d_in[8];
    const float* ch_b2  = (const float*)d_in[9];
    float* out = (float*)d_out;

    (void)in_sizes; (void)n_in;
    float* auxp = (out_size > Bq * Nn * Dd) ? (out + (size_t)Bq * Nn * Dd) : nullptr;

    mean_kernel<<<Bq, 256>>>(x);
    gate_kernel<<<1, 256>>>(rw, auxp);

    dim3 g1t((Dd / BM) * (HN / BN), E_TOK, Bq);   // 192 x 4 x 32
    gemm1_kernel<<<g1t, 256>>>(x, tok_w1, tok_b1, 1);

    dim3 g1c((Nn / BM) * (HD / BN), E_CH, Bq);    // 192 x 4 x 32
    gemm1_kernel<<<g1c, 256>>>(x, ch_w1, ch_b1, 0);

    dim3 g2((Nn / BM) * (Dd / BN), 1, Bq);        // 48 x 1 x 32
    gemm2_kernel<<<g2, 256>>>(tok_w2, tok_b2, ch_w2, ch_b2, out);
}

// round 3
// speedup vs baseline: 2.6767x; 2.6767x over previous
#include <cuda_runtime.h>
#include <cuda_bf16.h>
#include <math.h>
#include <stdint.h>

#define Bq    32
#define Nn    1024
#define Dd    768
#define E_TOK 4
#define E_CH  4
#define Ee    8
#define HN    4096
#define HD    3072

#define SLOT_STRIDE 3145728   // 768*4096 == 1024*3072

// ---------------- scratch (__device__ globals: sanctioned scratch path) -----
__device__ float g_xmean[Bq * Dd];
__device__ float g_combine[Bq * Ee];
__device__ int   g_slot[Bq * Ee];

__device__ __nv_bfloat16 g_xt_hi[(size_t)Bq * Dd * Nn];  // x^T  [b][d][n]
__device__ __nv_bfloat16 g_xt_lo[(size_t)Bq * Dd * Nn];
__device__ __nv_bfloat16 g_xc_hi[(size_t)Bq * Nn * Dd];  // x    [b][n][d]
__device__ __nv_bfloat16 g_xc_lo[(size_t)Bq * Nn * Dd];
__device__ __nv_bfloat16 g_w1t_hi[(size_t)E_TOK * HN * Nn];
__device__ __nv_bfloat16 g_w1t_lo[(size_t)E_TOK * HN * Nn];
__device__ __nv_bfloat16 g_w2t_hi[(size_t)E_TOK * Nn * HN];
__device__ __nv_bfloat16 g_w2t_lo[(size_t)E_TOK * Nn * HN];
__device__ __nv_bfloat16 g_w1c_hi[(size_t)E_CH * HD * Dd];
__device__ __nv_bfloat16 g_w1c_lo[(size_t)E_CH * HD * Dd];
__device__ __nv_bfloat16 g_w2c_hi[(size_t)E_CH * Dd * HD];
__device__ __nv_bfloat16 g_w2c_lo[(size_t)E_CH * Dd * HD];
__device__ __nv_bfloat16 g_hid_hi[(size_t)Bq * 2 * SLOT_STRIDE];
__device__ __nv_bfloat16 g_hid_lo[(size_t)Bq * 2 * SLOT_STRIDE];

// ---------------- smem geometry ---------------------------------------------
// Tile: 128(M) x 128(N) x 64(K) bf16. Row stride padded to 144B (72 halves):
// rows land on 16B-distinct banks mod 128 -> conflict-free ldmatrix + stores.
#define SKB      144
#define OP_BYTES (128 * SKB)        // 18432 per operand tile
#define ST_BYTES (4 * OP_BYTES)     // Ah, Al, Bh, Bl
#define SMEM_DYN (2 * ST_BYTES)     // 147456 (double buffered)

// ---------------- PTX helpers ------------------------------------------------
__device__ __forceinline__ uint32_t s2u(const void* p) {
    uint32_t a;
    asm("{ .reg .u64 t; cvta.to.shared.u64 t, %1; cvt.u32.u64 %0, t; }" : "=r"(a) : "l"(p));
    return a;
}
__device__ __forceinline__ void cp16(uint32_t sdst, const void* g) {
    asm volatile("cp.async.cg.shared.global [%0], [%1], 16;" :: "r"(sdst), "l"(g));
}
__device__ __forceinline__ void cp_commit() {
    asm volatile("cp.async.commit_group;" ::: "memory");
}
__device__ __forceinline__ void cp_wait1() {
    asm volatile("cp.async.wait_group 1;" ::: "memory");
}
__device__ __forceinline__ void cp_wait0() {
    asm volatile("cp.async.wait_group 0;" ::: "memory");
}
__device__ __forceinline__ void ldsm4(uint32_t* r, uint32_t addr) {
    asm volatile("ldmatrix.sync.aligned.m8n8.x4.shared.b16 {%0,%1,%2,%3}, [%4];"
                 : "=r"(r[0]), "=r"(r[1]), "=r"(r[2]), "=r"(r[3]) : "r"(addr));
}
__device__ __forceinline__ void mma16816(float* c, const uint32_t* a, const uint32_t* b) {
    asm volatile(
        "mma.sync.aligned.m16n8k16.row.col.f32.bf16.bf16.f32 "
        "{%0,%1,%2,%3}, {%4,%5,%6,%7}, {%8,%9}, {%0,%1,%2,%3};"
        : "+f"(c[0]), "+f"(c[1]), "+f"(c[2]), "+f"(c[3])
        : "r"(a[0]), "r"(a[1]), "r"(a[2]), "r"(a[3]), "r"(b[0]), "r"(b[1]));
}

__device__ __forceinline__ void split2(float v, __nv_bfloat16& h, __nv_bfloat16& l) {
    h = __float2bfloat16(v);
    l = __float2bfloat16(v - __bfloat162float(h));
}
__device__ __forceinline__ float gelu_tanh(float v) {
    float c = 0.7978845608028654f * (v + 0.044715f * v * v * v);
    return 0.5f * v * (1.0f + tanhf(c));
}

// ---------------- GEMM core --------------------------------------------------
// Load one 128x64-half operand tile (rows K-contiguous) into padded smem.
__device__ __forceinline__ void cpa_tile(uint32_t sdst, const __nv_bfloat16* __restrict__ g,
                                         int k0, int strideK, int tid) {
    #pragma unroll
    for (int i = 0; i < 4; i++) {
        int c = tid + i * 256;            // 1024 chunks of 16B
        int row = c >> 3, seg = c & 7;
        cp16(sdst + row * SKB + seg * 16,
             g + (size_t)row * strideK + k0 + seg * 8);
    }
}

__device__ __forceinline__ void issue_stage(uint32_t sbase,
                                            const __nv_bfloat16* Ah, const __nv_bfloat16* Al,
                                            const __nv_bfloat16* Bh, const __nv_bfloat16* Bl,
                                            int k0, int strideK, int tid) {
    cpa_tile(sbase,                Ah, k0, strideK, tid);
    cpa_tile(sbase + OP_BYTES,     Al, k0, strideK, tid);
    cpa_tile(sbase + 2 * OP_BYTES, Bh, k0, strideK, tid);
    cpa_tile(sbase + 3 * OP_BYTES, Bl, k0, strideK, tid);
    cp_commit();
}

// Compute one BK=64 stage: 4 k16-steps, warp tile 64x32, 3-term split.
__device__ __forceinline__ void compute_stage(uint32_t s, float acc[4][4][4],
                                              int wm, int wn, int lane) {
    uint32_t aRow = lane & 15;
    uint32_t aK   = (lane >> 4) * 8;
    uint32_t bRow = (lane & 7) + ((lane >> 4) & 1) * 8;
    uint32_t bK   = ((lane >> 3) & 1) * 8;
    #pragma unroll
    for (int ks = 0; ks < 4; ks++) {
        uint32_t bh[4][2], bl[4][2];
        #pragma unroll
        for (int half = 0; half < 2; half++) {
            uint32_t addr = s + 2 * OP_BYTES
                          + (wn * 32 + half * 16 + bRow) * SKB
                          + (ks * 16 + bK) * 2;
            uint32_t t[4];
            ldsm4(t, addr);
            bh[half * 2][0] = t[0]; bh[half * 2][1] = t[1];
            bh[half * 2 + 1][0] = t[2]; bh[half * 2 + 1][1] = t[3];
            ldsm4(t, addr + OP_BYTES);
            bl[half * 2][0] = t[0]; bl[half * 2][1] = t[1];
            bl[half * 2 + 1][0] = t[2]; bl[half * 2 + 1][1] = t[3];
        }
        #pragma unroll
        for (int mf = 0; mf < 4; mf++) {
            uint32_t addr = s + (wm * 64 + mf * 16 + aRow) * SKB + (ks * 16 + aK) * 2;
            uint32_t ah[4], al[4];
            ldsm4(ah, addr);
            ldsm4(al, addr + OP_BYTES);
            #pragma unroll
            for (int nf = 0; nf < 4; nf++) {
                mma16816(acc[mf][nf], ah, bh[nf]);
                mma16816(acc[mf][nf], ah, bl[nf]);
                mma16816(acc[mf][nf], al, bh[nf]);
            }
        }
    }
}

// Full pipelined K-loop over one operand set, accumulating into acc.
__device__ __forceinline__ void gemm_pipeline(uint32_t sb,
                                              const __nv_bfloat16* Ah, const __nv_bfloat16* Al,
                                              const __nv_bfloat16* Bh, const __nv_bfloat16* Bl,
                                              int K, float acc[4][4][4],
                                              int wm, int wn, int lane, int tid) {
    int nch = K / 64;
    issue_stage(sb, Ah, Al, Bh, Bl, 0, K, tid);
    for (int c = 0; c < nch; c++) {
        if (c + 1 < nch) {
            issue_stage(sb + ((c + 1) & 1) * ST_BYTES, Ah, Al, Bh, Bl, (c + 1) * 64, K, tid);
            cp_wait1();
        } else {
            cp_wait0();
        }
        __syncthreads();
        compute_stage(sb + (c & 1) * ST_BYTES, acc, wm, wn, lane);
        __syncthreads();
    }
}

// ---------------- router -----------------------------------------------------
__global__ void mean_kernel(const float* __restrict__ x) {
    int b = blockIdx.x;
    const float* xb = x + (size_t)b * Nn * Dd;
    for (int d = threadIdx.x; d < Dd; d += blockDim.x) {
        float s = 0.f;
        const float* p = xb + d;
        #pragma unroll 8
        for (int n = 0; n < Nn; n++) s += p[(size_t)n * Dd];
        g_xmean[b * Dd + d] = s * (1.0f / Nn);
    }
}

__global__ void gate_kernel(const float* __restrict__ rw, float* __restrict__ aux_out) {
    __shared__ float s_probs[Bq][Ee];
    __shared__ int   s_top1[Bq];
    int warp = threadIdx.x >> 5, lane = threadIdx.x & 31;
    int nwarp = blockDim.x >> 5;
    for (int b = warp; b < Bq; b += nwarp) {
        float logits[Ee];
        #pragma unroll
        for (int e = 0; e < Ee; e++) {
            float s = 0.f;
            for (int d = lane; d < Dd; d += 32)
                s += g_xmean[b * Dd + d] * rw[e * Dd + d];
            #pragma unroll
            for (int o = 16; o; o >>= 1) s += __shfl_xor_sync(0xffffffffu, s, o);
            logits[e] = s;
        }
        if (lane == 0) {
            float mx = logits[0];
            #pragma unroll
            for (int e = 1; e < Ee; e++) mx = fmaxf(mx, logits[e]);
            float p[Ee], se = 0.f;
            #pragma unroll
            for (int e = 0; e < Ee; e++) { p[e] = expf(logits[e] - mx); se += p[e]; }
            float inv = 1.0f / se;
            #pragma unroll
            for (int e = 0; e < Ee; e++) p[e] *= inv;
            int i0 = 0;
            #pragma unroll
            for (int e = 1; e < Ee; e++) if (p[e] > p[i0]) i0 = e;
            int i1 = (i0 == 0) ? 1 : 0;
            #pragma unroll
            for (int e = 0; e < Ee; e++) if (e != i1 && e != i0 && p[e] > p[i1]) i1 = e;
            float ws = p[i0] + p[i1];
            #pragma unroll
            for (int e = 0; e < Ee; e++) { g_combine[b * Ee + e] = 0.f; g_slot[b * Ee + e] = -1; }
            g_combine[b * Ee + i0] = p[i0] / ws;  g_slot[b * Ee + i0] = b * 2;
            g_combine[b * Ee + i1] = p[i1] / ws;  g_slot[b * Ee + i1] = b * 2 + 1;
            #pragma unroll
            for (int e = 0; e < Ee; e++) s_probs[b][e] = p[e];
            s_top1[b] = i0;
        }
    }
    __syncthreads();
    if (threadIdx.x == 0 && aux_out != nullptr) {
        float aux = 0.f;
        for (int e = 0; e < Ee; e++) {
            float pm = 0.f; int c = 0;
            for (int b = 0; b < Bq; b++) { pm += s_probs[b][e]; c += (s_top1[b] == e); }
            aux += (pm / Bq) * ((float)c / Bq);
        }
        aux_out[0] = (float)Ee * aux;
    }
}

// ---------------- conversion: fp32 -> bf16 hi/lo ----------------------------
__global__ void split_kernel(const float* __restrict__ in, __nv_bfloat16* __restrict__ hi,
                             __nv_bfloat16* __restrict__ lo, int n4) {
    int i = blockIdx.x * blockDim.x + threadIdx.x;
    if (i >= n4) return;
    float4 v = ((const float4*)in)[i];
    __nv_bfloat16 h0, l0, h1, l1, h2, l2, h3, l3;
    split2(v.x, h0, l0); split2(v.y, h1, l1); split2(v.z, h2, l2); split2(v.w, h3, l3);
    __nv_bfloat162 ph0; ph0.x = h0; ph0.y = h1;
    __nv_bfloat162 ph1; ph1.x = h2; ph1.y = h3;
    __nv_bfloat162 pl0; pl0.x = l0; pl0.y = l1;
    __nv_bfloat162 pl1; pl1.x = l2; pl1.y = l3;
    ((__nv_bfloat162*)hi)[2 * i]     = ph0;
    ((__nv_bfloat162*)hi)[2 * i + 1] = ph1;
    ((__nv_bfloat162*)lo)[2 * i]     = pl0;
    ((__nv_bfloat162*)lo)[2 * i + 1] = pl1;
}

__global__ void xt_split_kernel(const float* __restrict__ x) {
    __shared__ float t[32][33];
    int b = blockIdx.z;
    int d0 = blockIdx.x * 32, n0 = blockIdx.y * 32;
    int tx = threadIdx.x, ty = threadIdx.y;
    const float* xb = x + (size_t)b * Nn * Dd;
    #pragma unroll
    for (int k = 0; k < 32; k += 8)
        t[ty + k][tx] = xb[(size_t)(n0 + ty + k) * Dd + d0 + tx];
    __syncthreads();
    size_t base = (size_t)b * Dd * Nn;
    #pragma unroll
    for (int k = 0; k < 32; k += 8) {
        float v = t[tx][ty + k];
        __nv_bfloat16 h, l; split2(v, h, l);
        size_t idx = base + (size_t)(d0 + ty + k) * Nn + n0 + tx;
        g_xt_hi[idx] = h;
        g_xt_lo[idx] = l;
    }
}

// ---------------- GEMM1 ------------------------------------------------------
__global__ void __launch_bounds__(256, 1) gemm1_mma(const float* __restrict__ b1, int is_token) {
    extern __shared__ char smem[];
    int b = blockIdx.z, el = blockIdx.y;
    int eg = is_token ? el : (E_TOK + el);
    float w = g_combine[b * Ee + eg];
    if (w == 0.f) return;
    int slot = g_slot[b * Ee + eg];
    int Nh = is_token ? HN : HD;
    int K  = is_token ? Nn : Dd;
    int tilesN = Nh / 128;
    int m0 = (blockIdx.x / tilesN) * 128;
    int n0 = (blockIdx.x % tilesN) * 128;

    const __nv_bfloat16 *Ah, *Al, *Bh, *Bl;
    if (is_token) {
        size_t xo = (size_t)b * Dd * Nn + (size_t)m0 * Nn;
        Ah = g_xt_hi + xo; Al = g_xt_lo + xo;
        size_t wo = (size_t)el * HN * Nn + (size_t)n0 * Nn;
        Bh = g_w1t_hi + wo; Bl = g_w1t_lo + wo;
    } else {
        size_t xo = (size_t)b * Nn * Dd + (size_t)m0 * Dd;
        Ah = g_xc_hi + xo; Al = g_xc_lo + xo;
        size_t wo = (size_t)el * HD * Dd + (size_t)n0 * Dd;
        Bh = g_w1c_hi + wo; Bl = g_w1c_lo + wo;
    }

    uint32_t sb = s2u(smem);
    int tid = threadIdx.x, wid = tid >> 5, lane = tid & 31;
    int wm = wid >> 2, wn = wid & 3;

    float acc[4][4][4] = {};
    gemm_pipeline(sb, Ah, Al, Bh, Bl, K, acc, wm, wn, lane, tid);

    // epilogue: gelu(acc + b1) * w -> split bf16 hi/lo -> hid
    __nv_bfloat16* Hh = g_hid_hi + (size_t)slot * SLOT_STRIDE;
    __nv_bfloat16* Hl = g_hid_lo + (size_t)slot * SLOT_STRIDE;
    const float* b1e = b1 + el * Nh;
    #pragma unroll
    for (int mf = 0; mf < 4; mf++) {
        int m = m0 + wm * 64 + mf * 16 + (lane >> 2);
        #pragma unroll
        for (int nf = 0; nf < 4; nf++) {
            int col = n0 + wn * 32 + nf * 8 + (lane & 3) * 2;
            float bv0 = b1e[col], bv1 = b1e[col + 1];
            #pragma unroll
            for (int half = 0; half < 2; half++) {
                int mm = m + half * 8;
                float v0 = w * gelu_tanh(acc[mf][nf][half * 2]     + bv0);
                float v1 = w * gelu_tanh(acc[mf][nf][half * 2 + 1] + bv1);
                __nv_bfloat16 h0, l0, h1, l1;
                split2(v0, h0, l0); split2(v1, h1, l1);
                __nv_bfloat162 ph; ph.x = h0; ph.y = h1;
                __nv_bfloat162 pl; pl.x = l0; pl.y = l1;
                *(__nv_bfloat162*)(Hh + (size_t)mm * Nh + col) = ph;
                *(__nv_bfloat162*)(Hl + (size_t)mm * Nh + col) = pl;
            }
        }
    }
}

// ---------------- GEMM2 ------------------------------------------------------
__global__ void __launch_bounds__(256, 1) gemm2_mma(const float* __restrict__ tok_b2,
                                                    const float* __restrict__ ch_b2,
                                                    float* __restrict__ out) {
    extern __shared__ char smem[];
    int b = blockIdx.z;
    int n0 = (blockIdx.x / 6) * 128;
    int d0 = (blockIdx.x % 6) * 128;

    int ae[2]; float aw[2]; int cnt = 0;
    #pragma unroll
    for (int e = 0; e < Ee; e++) {
        float wv = g_combine[b * Ee + e];
        if (wv != 0.f && cnt < 2) { ae[cnt] = e; aw[cnt] = wv; cnt++; }
    }

    uint32_t sb = s2u(smem);
    int tid = threadIdx.x, wid = tid >> 5, lane = tid & 31;
    int wm = wid >> 2, wn = wid & 3;

    float acc[4][4][4] = {};
    for (int xi = 0; xi < cnt; xi++) {
        int e = ae[xi];
        int slot = g_slot[b * Ee + e];
        const __nv_bfloat16 *Ah, *Al, *Bh, *Bl;
        int K;
        if (e < E_TOK) {
            size_t ao = (size_t)e * Nn * HN + (size_t)n0 * HN;
            Ah = g_w2t_hi + ao; Al = g_w2t_lo + ao;
            size_t bo = (size_t)slot * SLOT_STRIDE + (size_t)d0 * HN;
            Bh = g_hid_hi + bo; Bl = g_hid_lo + bo;
            K = HN;
        } else {
            int el = e - E_TOK;
            size_t ao = (size_t)slot * SLOT_STRIDE + (size_t)n0 * HD;
            Ah = g_hid_hi + ao; Al = g_hid_lo + ao;
            size_t bo = (size_t)el * Dd * HD + (size_t)d0 * HD;
            Bh = g_w2c_hi + bo; Bl = g_w2c_lo + bo;
            K = HD;
        }
        gemm_pipeline(sb, Ah, Al, Bh, Bl, K, acc, wm, wn, lane, tid);
    }

    // epilogue: + combine-weighted biases, store fp32
    #pragma unroll
    for (int mf = 0; mf < 4; mf++) {
        int m = n0 + wm * 64 + mf * 16 + (lane >> 2);
        #pragma unroll
        for (int half = 0; half < 2; half++) {
            int mm = m + half * 8;
            float rowb = 0.f;
            #pragma unroll
            for (int xi = 0; xi < 2; xi++)
                if (xi < cnt && ae[xi] < E_TOK) rowb += aw[xi] * tok_b2[ae[xi] * Nn + mm];
            float* orow = out + ((size_t)b * Nn + mm) * Dd;
            #pragma unroll
            for (int nf = 0; nf < 4; nf++) {
                int col = d0 + wn * 32 + nf * 8 + (lane & 3) * 2;
                float cb0 = 0.f, cb1 = 0.f;
                #pragma unroll
                for (int xi = 0; xi < 2; xi++)
                    if (xi < cnt && ae[xi] >= E_TOK) {
                        const float* cb = ch_b2 + (ae[xi] - E_TOK) * Dd;
                        cb0 += aw[xi] * cb[col];
                        cb1 += aw[xi] * cb[col + 1];
                    }
                float2 v;
                v.x = acc[mf][nf][half * 2]     + rowb + cb0;
                v.y = acc[mf][nf][half * 2 + 1] + rowb + cb1;
                *(float2*)(orow + col) = v;
            }
        }
    }
}

// ---------------- launch -----------------------------------------------------
extern "C" void kernel_launch(void* const* d_in, const int* in_sizes, int n_in,
                              void* d_out, int out_size) {
    const float* x      = (const float*)d_in[0];
    const float* rw     = (const float*)d_in[1];
    const float* tok_w1 = (const float*)d_in[2];
    const float* tok_b1 = (const float*)d_in[3];
    const float* tok_w2 = (const float*)d_in[4];
    const float* tok_b2 = (const float*)d_in[5];
    const float* ch_w1  = (const float*)d_in[6];
    const float* ch_b1  = (const float*)d_in[7];
    const float* ch_w2  = (const float*)d_in[8];
    const float* ch_b2  = (const float*)d_in[9];
    float* out = (float*)d_out;
    (void)in_sizes; (void)n_in;
    float* auxp = (out_size > Bq * Nn * Dd) ? (out + (size_t)Bq * Nn * Dd) : nullptr;

    cudaFuncSetAttribute(gemm1_mma, cudaFuncAttributeMaxDynamicSharedMemorySize, SMEM_DYN);
    cudaFuncSetAttribute(gemm2_mma, cudaFuncAttributeMaxDynamicSharedMemorySize, SMEM_DYN);

    mean_kernel<<<Bq, 256>>>(x);
    gate_kernel<<<1, 256>>>(rw, auxp);

    {
        __nv_bfloat16 *p_xc_hi, *p_xc_lo, *p_w1t_hi, *p_w1t_lo, *p_w2t_hi, *p_w2t_lo;
        __nv_bfloat16 *p_w1c_hi, *p_w1c_lo, *p_w2c_hi, *p_w2c_lo;
        cudaGetSymbolAddress((void**)&p_xc_hi,  g_xc_hi);
        cudaGetSymbolAddress((void**)&p_xc_lo,  g_xc_lo);
        cudaGetSymbolAddress((void**)&p_w1t_hi, g_w1t_hi);
        cudaGetSymbolAddress((void**)&p_w1t_lo, g_w1t_lo);
        cudaGetSymbolAddress((void**)&p_w2t_hi, g_w2t_hi);
        cudaGetSymbolAddress((void**)&p_w2t_lo, g_w2t_lo);
        cudaGetSymbolAddress((void**)&p_w1c_hi, g_w1c_hi);
        cudaGetSymbolAddress((void**)&p_w1c_lo, g_w1c_lo);
        cudaGetSymbolAddress((void**)&p_w2c_hi, g_w2c_hi);
        cudaGetSymbolAddress((void**)&p_w2c_lo, g_w2c_lo);

        int n4x = Bq * Nn * Dd / 4;
        split_kernel<<<(n4x + 255) / 256, 256>>>(x, p_xc_hi, p_xc_lo, n4x);
        xt_split_kernel<<<dim3(Dd / 32, Nn / 32, Bq), dim3(32, 8)>>>(x);
        int n4a = E_TOK * HN * Nn / 4;
        split_kernel<<<(n4a + 255) / 256, 256>>>(tok_w1, p_w1t_hi, p_w1t_lo, n4a);
        split_kernel<<<(n4a + 255) / 256, 256>>>(tok_w2, p_w2t_hi, p_w2t_lo, n4a);
        int n4c = E_CH * HD * Dd / 4;
        split_kernel<<<(n4c + 255) / 256, 256>>>(ch_w1, p_w1c_hi, p_w1c_lo, n4c);
        split_kernel<<<(n4c + 255) / 256, 256>>>(ch_w2, p_w2c_hi, p_w2c_lo, n4c);
    }

    dim3 g1t((Dd / 128) * (HN / 128), E_TOK, Bq);   // 192 x 4 x 32
    gemm1_mma<<<g1t, 256, SMEM_DYN>>>(tok_b1, 1);
    dim3 g1c((Nn / 128) * (HD / 128), E_CH, Bq);    // 192 x 4 x 32
    gemm1_mma<<<g1c, 256, SMEM_DYN>>>(ch_b1, 0);

    dim3 g2((Nn / 128) * (Dd / 128), 1, Bq);        // 48 x 1 x 32
    gemm2_mma<<<g2, 256, SMEM_DYN>>>(tok_b2, ch_b2, out);
}

// round 4
// speedup vs baseline: 6.7583x; 2.5248x over previous
#include <cuda_runtime.h>
#include <cuda_fp16.h>
#include <math.h>
#include <stdint.h>

#define Bq    32
#define Nn    1024
#define Dd    768
#define E_TOK 4
#define E_CH  4
#define Ee    8
#define HN    4096
#define HD    3072

#define SLOT_STRIDE 3145728   // 768*4096 == 1024*3072

// ---------------- scratch (__device__ globals: sanctioned scratch path) -----
__device__ float g_xmean[Bq * Dd];
__device__ float g_combine[Bq * Ee];
__device__ int   g_slot[Bq * Ee];

__device__ __half g_xt [(size_t)Bq * Dd * Nn];   // x^T [b][d][n]
__device__ __half g_xc [(size_t)Bq * Nn * Dd];   // x   [b][n][d]
__device__ __half g_w1t[(size_t)E_TOK * HN * Nn];
__device__ __half g_w2t[(size_t)E_TOK * Nn * HN];
__device__ __half g_w1c[(size_t)E_CH * HD * Dd];
__device__ __half g_w2c[(size_t)E_CH * Dd * HD];
__device__ __half g_hid[(size_t)Bq * 2 * SLOT_STRIDE];

// ---------------- smem geometry ---------------------------------------------
// CTA tile 128(M) x 256(N) x 64(K) fp16. Row stride 144B: rows shift 16B mod 128
// -> conflict-free ldmatrix (validated in R3).
#define BM 128
#define BN 256
#define BK 64
#define SKB 144
#define A_BYTES (BM * SKB)             // 18432
#define B_BYTES (BN * SKB)             // 36864
#define ST_BYTES (A_BYTES + B_BYTES)   // 55296
#define NSTAGE 4
#define SMEM_DYN (NSTAGE * ST_BYTES)   // 221184

// ---------------- PTX helpers ------------------------------------------------
__device__ __forceinline__ uint32_t s2u(const void* p) {
    uint32_t a;
    asm("{ .reg .u64 t; cvta.to.shared.u64 t, %1; cvt.u32.u64 %0, t; }" : "=r"(a) : "l"(p));
    return a;
}
__device__ __forceinline__ void cp16(uint32_t sdst, const void* g) {
    asm volatile("cp.async.cg.shared.global [%0], [%1], 16;" :: "r"(sdst), "l"(g));
}
__device__ __forceinline__ void cp_commit() { asm volatile("cp.async.commit_group;" ::: "memory"); }
__device__ __forceinline__ void cp_wait2() { asm volatile("cp.async.wait_group 2;" ::: "memory"); }
__device__ __forceinline__ void cp_wait1() { asm volatile("cp.async.wait_group 1;" ::: "memory"); }
__device__ __forceinline__ void cp_wait0() { asm volatile("cp.async.wait_group 0;" ::: "memory"); }
__device__ __forceinline__ void ldsm4(uint32_t* r, uint32_t addr) {
    asm volatile("ldmatrix.sync.aligned.m8n8.x4.shared.b16 {%0,%1,%2,%3}, [%4];"
                 : "=r"(r[0]), "=r"(r[1]), "=r"(r[2]), "=r"(r[3]) : "r"(addr));
}
__device__ __forceinline__ void mma_f16(float* c, const uint32_t* a, const uint32_t* b) {
    asm volatile(
        "mma.sync.aligned.m16n8k16.row.col.f32.f16.f16.f32 "
        "{%0,%1,%2,%3}, {%4,%5,%6,%7}, {%8,%9}, {%0,%1,%2,%3};"
        : "+f"(c[0]), "+f"(c[1]), "+f"(c[2]), "+f"(c[3])
        : "r"(a[0]), "r"(a[1]), "r"(a[2]), "r"(a[3]), "r"(b[0]), "r"(b[1]));
}
__device__ __forceinline__ float gelu_tanh(float v) {
    float c = 0.7978845608028654f * (v + 0.044715f * v * v * v);
    return 0.5f * v * (1.0f + tanhf(c));
}

// ---------------- GEMM core --------------------------------------------------
template <int R>
__device__ __forceinline__ void cpa_tile(uint32_t sdst, const __half* __restrict__ g,
                                         int k0, int strideK, int tid) {
    #pragma unroll
    for (int i = 0; i < R * 8 / 256; i++) {
        int c = tid + i * 256;
        int row = c >> 3, seg = c & 7;
        cp16(sdst + row * SKB + seg * 16,
             g + (size_t)row * strideK + k0 + seg * 8);
    }
}

__device__ __forceinline__ void issue_stage(uint32_t sbase,
                                            const __half* A, const __half* B,
                                            int k0, int strideK, int tid) {
    cpa_tile<BM>(sbase, A, k0, strideK, tid);
    cpa_tile<BN>(sbase + A_BYTES, B, k0, strideK, tid);
    cp_commit();
}

__device__ __forceinline__ void compute_stage(uint32_t s, float acc[4][8][4],
                                              int wm, int wn, int lane) {
    uint32_t aRow = lane & 15;
    uint32_t aK   = (lane >> 4) * 8;
    uint32_t bRow = (lane & 7) + ((lane >> 4) & 1) * 8;
    uint32_t bK   = ((lane >> 3) & 1) * 8;
    uint32_t sA = s, sB = s + A_BYTES;
    #pragma unroll
    for (int ks = 0; ks < 4; ks++) {
        uint32_t b[8][2];
        #pragma unroll
        for (int q = 0; q < 4; q++) {
            uint32_t t[4];
            ldsm4(t, sB + (wn * 64 + q * 16 + bRow) * SKB + (ks * 16 + bK) * 2);
            b[q * 2][0] = t[0]; b[q * 2][1] = t[1];
            b[q * 2 + 1][0] = t[2]; b[q * 2 + 1][1] = t[3];
        }
        #pragma unroll
        for (int mf = 0; mf < 4; mf++) {
            uint32_t a[4];
            ldsm4(a, sA + (wm * 64 + mf * 16 + aRow) * SKB + (ks * 16 + aK) * 2);
            #pragma unroll
            for (int nf = 0; nf < 8; nf++)
                mma_f16(acc[mf][nf], a, b[nf]);
        }
    }
}

// 4-stage cp.async pipeline, single __syncthreads per stage.
__device__ __forceinline__ void gemm_pipeline(uint32_t sb,
                                              const __half* A, const __half* B, int K,
                                              float acc[4][8][4],
                                              int wm, int wn, int lane, int tid) {
    int nch = K / BK;   // always >= 4 and divisible by 4 here
    issue_stage(sb,                A, B, 0,      K, tid);
    issue_stage(sb + ST_BYTES,     A, B, BK,     K, tid);
    issue_stage(sb + 2 * ST_BYTES, A, B, 2 * BK, K, tid);
    for (int c = 0; c < nch; c++) {
        int rem = nch - 1 - c;
        if (rem >= 2) cp_wait2(); else if (rem == 1) cp_wait1(); else cp_wait0();
        __syncthreads();
        compute_stage(sb + (c & 3) * ST_BYTES, acc, wm, wn, lane);
        if (c + 3 < nch)
            issue_stage(sb + ((c + 3) & 3) * ST_BYTES, A, B, (c + 3) * BK, K, tid);
    }
    // nch % 4 == 0 -> last-read buffer is 3; next pipeline's prologue (buffers
    // 0,1,2) is safe: all warps passed the final sync having consumed them.
}

// ---------------- router -----------------------------------------------------
__global__ void mean_kernel(const float* __restrict__ x) {
    int b = blockIdx.x;
    const float* xb = x + (size_t)b * Nn * Dd;
    for (int d = threadIdx.x; d < Dd; d += blockDim.x) {
        float s = 0.f;
        const float* p = xb + d;
        #pragma unroll 8
        for (int n = 0; n < Nn; n++) s += p[(size_t)n * Dd];
        g_xmean[b * Dd + d] = s * (1.0f / Nn);
    }
}

__global__ void gate_kernel(const float* __restrict__ rw, float* __restrict__ aux_out) {
    __shared__ float s_probs[Bq][Ee];
    __shared__ int   s_top1[Bq];
    int warp = threadIdx.x >> 5, lane = threadIdx.x & 31;
    int nwarp = blockDim.x >> 5;
    for (int b = warp; b < Bq; b += nwarp) {
        float logits[Ee];
        #pragma unroll
        for (int e = 0; e < Ee; e++) {
            float s = 0.f;
            for (int d = lane; d < Dd; d += 32)
                s += g_xmean[b * Dd + d] * rw[e * Dd + d];
            #pragma unroll
            for (int o = 16; o; o >>= 1) s += __shfl_xor_sync(0xffffffffu, s, o);
            logits[e] = s;
        }
        if (lane == 0) {
            float mx = logits[0];
            #pragma unroll
            for (int e = 1; e < Ee; e++) mx = fmaxf(mx, logits[e]);
            float p[Ee], se = 0.f;
            #pragma unroll
            for (int e = 0; e < Ee; e++) { p[e] = expf(logits[e] - mx); se += p[e]; }
            float inv = 1.0f / se;
            #pragma unroll
            for (int e = 0; e < Ee; e++) p[e] *= inv;
            int i0 = 0;
            #pragma unroll
            for (int e = 1; e < Ee; e++) if (p[e] > p[i0]) i0 = e;
            int i1 = (i0 == 0) ? 1 : 0;
            #pragma unroll
            for (int e = 0; e < Ee; e++) if (e != i1 && e != i0 && p[e] > p[i1]) i1 = e;
            float ws = p[i0] + p[i1];
            #pragma unroll
            for (int e = 0; e < Ee; e++) { g_combine[b * Ee + e] = 0.f; g_slot[b * Ee + e] = -1; }
            g_combine[b * Ee + i0] = p[i0] / ws;  g_slot[b * Ee + i0] = b * 2;
            g_combine[b * Ee + i1] = p[i1] / ws;  g_slot[b * Ee + i1] = b * 2 + 1;
            #pragma unroll
            for (int e = 0; e < Ee; e++) s_probs[b][e] = p[e];
            s_top1[b] = i0;
        }
    }
    __syncthreads();
    if (threadIdx.x == 0 && aux_out != nullptr) {
        float aux = 0.f;
        for (int e = 0; e < Ee; e++) {
            float pm = 0.f; int c = 0;
            for (int b = 0; b < Bq; b++) { pm += s_probs[b][e]; c += (s_top1[b] == e); }
            aux += (pm / Bq) * ((float)c / Bq);
        }
        aux_out[0] = (float)Ee * aux;
    }
}

// ---------------- conversions ------------------------------------------------
__global__ void cvt_kernel(const float* __restrict__ in, __half* __restrict__ out, int n4) {
    int i = blockIdx.x * blockDim.x + threadIdx.x;
    if (i >= n4) return;
    float4 v = ((const float4*)in)[i];
    __half2 h0 = __floats2half2_rn(v.x, v.y);
    __half2 h1 = __floats2half2_rn(v.z, v.w);
    ((__half2*)out)[2 * i]     = h0;
    ((__half2*)out)[2 * i + 1] = h1;
}

__global__ void xt_kernel(const float* __restrict__ x) {
    __shared__ float t[32][33];
    int b = blockIdx.z;
    int d0 = blockIdx.x * 32, n0 = blockIdx.y * 32;
    int tx = threadIdx.x, ty = threadIdx.y;
    const float* xb = x + (size_t)b * Nn * Dd;
    #pragma unroll
    for (int k = 0; k < 32; k += 8)
        t[ty + k][tx] = xb[(size_t)(n0 + ty + k) * Dd + d0 + tx];
    __syncthreads();
    size_t base = (size_t)b * Dd * Nn;
    #pragma unroll
    for (int k = 0; k < 32; k += 8)
        g_xt[base + (size_t)(d0 + ty + k) * Nn + n0 + tx] = __float2half_rn(t[tx][ty + k]);
}

// ---------------- GEMM1 ------------------------------------------------------
__global__ void __launch_bounds__(256, 1) gemm1_mma(const float* __restrict__ b1, int is_token) {
    extern __shared__ char smem[];
    int b = blockIdx.z, el = blockIdx.y;
    int eg = is_token ? el : (E_TOK + el);
    float w = g_combine[b * Ee + eg];
    if (w == 0.f) return;
    int slot = g_slot[b * Ee + eg];
    int Nh = is_token ? HN : HD;
    int K  = is_token ? Nn : Dd;
    int tilesN = Nh / BN;
    int m0 = (blockIdx.x / tilesN) * BM;
    int n0 = (blockIdx.x % tilesN) * BN;

    const __half *A, *B;
    if (is_token) {
        A = g_xt  + (size_t)b  * Dd * Nn + (size_t)m0 * Nn;
        B = g_w1t + (size_t)el * HN * Nn + (size_t)n0 * Nn;
    } else {
        A = g_xc  + (size_t)b  * Nn * Dd + (size_t)m0 * Dd;
        B = g_w1c + (size_t)el * HD * Dd + (size_t)n0 * Dd;
    }

    uint32_t sb = s2u(smem);
    int tid = threadIdx.x, wid = tid >> 5, lane = tid & 31;
    int wm = wid >> 2, wn = wid & 3;

    float acc[4][8][4] = {};
    gemm_pipeline(sb, A, B, K, acc, wm, wn, lane, tid);

    // epilogue: gelu(acc + b1) * w -> fp16 hidden
    __half* H = g_hid + (size_t)slot * SLOT_STRIDE;
    const float* b1e = b1 + el * Nh;
    #pragma unroll
    for (int mf = 0; mf < 4; mf++) {
        int m = m0 + wm * 64 + mf * 16 + (lane >> 2);
        #pragma unroll
        for (int nf = 0; nf < 8; nf++) {
            int col = n0 + wn * 64 + nf * 8 + (lane & 3) * 2;
            float bv0 = b1e[col], bv1 = b1e[col + 1];
            #pragma unroll
            for (int half = 0; half < 2; half++) {
                int mm = m + half * 8;
                float v0 = w * gelu_tanh(acc[mf][nf][half * 2]     + bv0);
                float v1 = w * gelu_tanh(acc[mf][nf][half * 2 + 1] + bv1);
                *(__half2*)(H + (size_t)mm * Nh + col) = __floats2half2_rn(v0, v1);
            }
        }
    }
}

// ---------------- GEMM2 ------------------------------------------------------
__global__ void __launch_bounds__(256, 1) gemm2_mma(const float* __restrict__ tok_b2,
                                                    const float* __restrict__ ch_b2,
                                                    float* __restrict__ out) {
    extern __shared__ char smem[];
    int b = blockIdx.z;
    int n0 = (blockIdx.x / (Dd / BN)) * BM;
    int d0 = (blockIdx.x % (Dd / BN)) * BN;

    int ae[2]; float aw[2]; int cnt = 0;
    #pragma unroll
    for (int e = 0; e < Ee; e++) {
        float wv = g_combine[b * Ee + e];
        if (wv != 0.f && cnt < 2) { ae[cnt] = e; aw[cnt] = wv; cnt++; }
    }

    uint32_t sb = s2u(smem);
    int tid = threadIdx.x, wid = tid >> 5, lane = tid & 31;
    int wm = wid >> 2, wn = wid & 3;

    float acc[4][8][4] = {};
    for (int xi = 0; xi < cnt; xi++) {
        int e = ae[xi];
        int slot = g_slot[b * Ee + e];
        const __half *A, *B;
        int K;
        if (e < E_TOK) {
            A = g_w2t + (size_t)e * Nn * HN + (size_t)n0 * HN;
            B = g_hid + (size_t)slot * SLOT_STRIDE + (size_t)d0 * HN;
            K = HN;
        } else {
            A = g_hid + (size_t)slot * SLOT_STRIDE + (size_t)n0 * HD;
            B = g_w2c + (size_t)(e - E_TOK) * Dd * HD + (size_t)d0 * HD;
            K = HD;
        }
        gemm_pipeline(sb, A, B, K, acc, wm, wn, lane, tid);
    }

    // epilogue: + combine-weighted biases, fp32 store
    #pragma unroll
    for (int mf = 0; mf < 4; mf++) {
        int m = n0 + wm * 64 + mf * 16 + (lane >> 2);
        #pragma unroll
        for (int half = 0; half < 2; half++) {
            int mm = m + half * 8;
            float rowb = 0.f;
            #pragma unroll
            for (int xi = 0; xi < 2; xi++)
                if (xi < cnt && ae[xi] < E_TOK) rowb += aw[xi] * tok_b2[ae[xi] * Nn + mm];
            float* orow = out + ((size_t)b * Nn + mm) * Dd;
            #pragma unroll
            for (int nf = 0; nf < 8; nf++) {
                int col = d0 + wn * 64 + nf * 8 + (lane & 3) * 2;
                float cb0 = 0.f, cb1 = 0.f;
                #pragma unroll
                for (int xi = 0; xi < 2; xi++)
                    if (xi < cnt && ae[xi] >= E_TOK) {
                        const float* cb = ch_b2 + (ae[xi] - E_TOK) * Dd;
                        cb0 += aw[xi] * cb[col];
                        cb1 += aw[xi] * cb[col + 1];
                    }
                float2 v;
                v.x = acc[mf][nf][half * 2]     + rowb + cb0;
                v.y = acc[mf][nf][half * 2 + 1] + rowb + cb1;
                *(float2*)(orow + col) = v;
            }
        }
    }
}

// ---------------- launch -----------------------------------------------------
extern "C" void kernel_launch(void* const* d_in, const int* in_sizes, int n_in,
                              void* d_out, int out_size) {
    const float* x      = (const float*)d_in[0];
    const float* rw     = (const float*)d_in[1];
    const float* tok_w1 = (const float*)d_in[2];
    const float* tok_b1 = (const float*)d_in[3];
    const float* tok_w2 = (const float*)d_in[4];
    const float* tok_b2 = (const float*)d_in[5];
    const float* ch_w1  = (const float*)d_in[6];
    const float* ch_b1  = (const float*)d_in[7];
    const float* ch_w2  = (const float*)d_in[8];
    const float* ch_b2  = (const float*)d_in[9];
    float* out = (float*)d_out;
    (void)in_sizes; (void)n_in;
    float* auxp = (out_size > Bq * Nn * Dd) ? (out + (size_t)Bq * Nn * Dd) : nullptr;

    cudaFuncSetAttribute(gemm1_mma, cudaFuncAttributeMaxDynamicSharedMemorySize, SMEM_DYN);
    cudaFuncSetAttribute(gemm2_mma, cudaFuncAttributeMaxDynamicSharedMemorySize, SMEM_DYN);

    mean_kernel<<<Bq, 256>>>(x);
    gate_kernel<<<1, 256>>>(rw, auxp);

    {
        __half *p_xc, *p_w1t, *p_w2t, *p_w1c, *p_w2c;
        cudaGetSymbolAddress((void**)&p_xc,  g_xc);
        cudaGetSymbolAddress((void**)&p_w1t, g_w1t);
        cudaGetSymbolAddress((void**)&p_w2t, g_w2t);
        cudaGetSymbolAddress((void**)&p_w1c, g_w1c);
        cudaGetSymbolAddress((void**)&p_w2c, g_w2c);

        int n4x = Bq * Nn * Dd / 4;
        cvt_kernel<<<(n4x + 255) / 256, 256>>>(x, p_xc, n4x);
        xt_kernel<<<dim3(Dd / 32, Nn / 32, Bq), dim3(32, 8)>>>(x);
        int n4a = E_TOK * HN * Nn / 4;
        cvt_kernel<<<(n4a + 255) / 256, 256>>>(tok_w1, p_w1t, n4a);
        cvt_kernel<<<(n4a + 255) / 256, 256>>>(tok_w2, p_w2t, n4a);
        int n4c = E_CH * HD * Dd / 4;
        cvt_kernel<<<(n4c + 255) / 256, 256>>>(ch_w1, p_w1c, n4c);
        cvt_kernel<<<(n4c + 255) / 256, 256>>>(ch_w2, p_w2c, n4c);
    }

    dim3 g1t((Dd / BM) * (HN / BN), E_TOK, Bq);   // 96 x 4 x 32
    gemm1_mma<<<g1t, 256, SMEM_DYN>>>(tok_b1, 1);
    dim3 g1c((Nn / BM) * (HD / BN), E_CH, Bq);    // 96 x 4 x 32
    gemm1_mma<<<g1c, 256, SMEM_DYN>>>(ch_b1, 0);

    dim3 g2((Nn / BM) * (Dd / BN), 1, Bq);        // 24 x 1 x 32
    gemm2_mma<<<g2, 256, SMEM_DYN>>>(tok_b2, ch_b2, out);
}

// round 5
// speedup vs baseline: 7.2810x; 1.0774x over previous
#include <cuda_runtime.h>
#include <cuda_fp16.h>
#include <math.h>
#include <stdint.h>

#define Bq    32
#define Nn    1024
#define Dd    768
#define E_TOK 4
#define E_CH  4
#define Ee    8
#define HN    4096
#define HD    3072

#define SLOT_STRIDE 3145728   // 768*4096 == 1024*3072

// ---------------- scratch (__device__ globals: sanctioned scratch path) -----
__device__ float g_pmean[Bq * 8 * Dd];
__device__ float g_xmean[Bq * Dd];
__device__ float g_combine[Bq * Ee];
__device__ int   g_slot[Bq * Ee];

__device__ __half g_xt [(size_t)Bq * Dd * Nn];   // x^T [b][d][n]
__device__ __half g_xc [(size_t)Bq * Nn * Dd];   // x   [b][n][d]
__device__ __half g_w1t[(size_t)E_TOK * HN * Nn];
__device__ __half g_w2t[(size_t)E_TOK * Nn * HN];
__device__ __half g_w1c[(size_t)E_CH * HD * Dd];
__device__ __half g_w2c[(size_t)E_CH * Dd * HD];
__device__ __half g_hid[(size_t)Bq * 2 * SLOT_STRIDE];

// ---------------- smem geometry ---------------------------------------------
#define BM 128
#define BN 256
#define BK 64
#define SKB 144
#define A_BYTES (BM * SKB)
#define B_BYTES (BN * SKB)
#define ST_BYTES (A_BYTES + B_BYTES)   // 55296
#define NSTAGE 4
#define SMEM_DYN (NSTAGE * ST_BYTES)   // 221184

// ---------------- PTX helpers ------------------------------------------------
__device__ __forceinline__ uint32_t s2u(const void* p) {
    uint32_t a;
    asm("{ .reg .u64 t; cvta.to.shared.u64 t, %1; cvt.u32.u64 %0, t; }" : "=r"(a) : "l"(p));
    return a;
}
__device__ __forceinline__ void cp16(uint32_t sdst, const void* g) {
    asm volatile("cp.async.cg.shared.global [%0], [%1], 16;" :: "r"(sdst), "l"(g));
}
__device__ __forceinline__ void cp_commit() { asm volatile("cp.async.commit_group;" ::: "memory"); }
__device__ __forceinline__ void cp_wait2() { asm volatile("cp.async.wait_group 2;" ::: "memory"); }
__device__ __forceinline__ void cp_wait1() { asm volatile("cp.async.wait_group 1;" ::: "memory"); }
__device__ __forceinline__ void cp_wait0() { asm volatile("cp.async.wait_group 0;" ::: "memory"); }
__device__ __forceinline__ void ldsm4(uint32_t* r, uint32_t addr) {
    asm volatile("ldmatrix.sync.aligned.m8n8.x4.shared.b16 {%0,%1,%2,%3}, [%4];"
                 : "=r"(r[0]), "=r"(r[1]), "=r"(r[2]), "=r"(r[3]) : "r"(addr));
}
__device__ __forceinline__ void mma_f16(float* c, const uint32_t* a, const uint32_t* b) {
    asm volatile(
        "mma.sync.aligned.m16n8k16.row.col.f32.f16.f16.f32 "
        "{%0,%1,%2,%3}, {%4,%5,%6,%7}, {%8,%9}, {%0,%1,%2,%3};"
        : "+f"(c[0]), "+f"(c[1]), "+f"(c[2]), "+f"(c[3])
        : "r"(a[0]), "r"(a[1]), "r"(a[2]), "r"(a[3]), "r"(b[0]), "r"(b[1]));
}
// streaming stores (evict-first: protect L2 read-reuse set)
__device__ __forceinline__ void stcs_u16(__half* p, __half v) {
    unsigned short u = *reinterpret_cast<unsigned short*>(&v);
    asm volatile("st.global.cs.u16 [%0], %1;" :: "l"(p), "h"(u) : "memory");
}
__device__ __forceinline__ void stcs_u32(void* p, uint32_t v) {
    asm volatile("st.global.cs.u32 [%0], %1;" :: "l"(p), "r"(v) : "memory");
}
__device__ __forceinline__ void stcs_v2u32(void* p, uint32_t a, uint32_t b) {
    asm volatile("st.global.cs.v2.u32 [%0], {%1, %2};" :: "l"(p), "r"(a), "r"(b) : "memory");
}
__device__ __forceinline__ void stcs_v2f32(void* p, float a, float b) {
    asm volatile("st.global.cs.v2.f32 [%0], {%1, %2};" :: "l"(p), "f"(a), "f"(b) : "memory");
}
__device__ __forceinline__ float gelu_tanh(float v) {
    float c = 0.7978845608028654f * (v + 0.044715f * v * v * v);
    return 0.5f * v * (1.0f + tanhf(c));
}

// ---------------- GEMM core (unchanged from R4, validated) -------------------
template <int R>
__device__ __forceinline__ void cpa_tile(uint32_t sdst, const __half* __restrict__ g,
                                         int k0, int strideK, int tid) {
    #pragma unroll
    for (int i = 0; i < R * 8 / 256; i++) {
        int c = tid + i * 256;
        int row = c >> 3, seg = c & 7;
        cp16(sdst + row * SKB + seg * 16,
             g + (size_t)row * strideK + k0 + seg * 8);
    }
}

__device__ __forceinline__ void issue_stage(uint32_t sbase,
                                            const __half* A, const __half* B,
                                            int k0, int strideK, int tid) {
    cpa_tile<BM>(sbase, A, k0, strideK, tid);
    cpa_tile<BN>(sbase + A_BYTES, B, k0, strideK, tid);
    cp_commit();
}

__device__ __forceinline__ void compute_stage(uint32_t s, float acc[4][8][4],
                                              int wm, int wn, int lane) {
    uint32_t aRow = lane & 15;
    uint32_t aK   = (lane >> 4) * 8;
    uint32_t bRow = (lane & 7) + ((lane >> 4) & 1) * 8;
    uint32_t bK   = ((lane >> 3) & 1) * 8;
    uint32_t sA = s, sB = s + A_BYTES;
    #pragma unroll
    for (int ks = 0; ks < 4; ks++) {
        uint32_t b[8][2];
        #pragma unroll
        for (int q = 0; q < 4; q++) {
            uint32_t t[4];
            ldsm4(t, sB + (wn * 64 + q * 16 + bRow) * SKB + (ks * 16 + bK) * 2);
            b[q * 2][0] = t[0]; b[q * 2][1] = t[1];
            b[q * 2 + 1][0] = t[2]; b[q * 2 + 1][1] = t[3];
        }
        #pragma unroll
        for (int mf = 0; mf < 4; mf++) {
            uint32_t a[4];
            ldsm4(a, sA + (wm * 64 + mf * 16 + aRow) * SKB + (ks * 16 + aK) * 2);
            #pragma unroll
            for (int nf = 0; nf < 8; nf++)
                mma_f16(acc[mf][nf], a, b[nf]);
        }
    }
}

__device__ __forceinline__ void gemm_pipeline(uint32_t sb,
                                              const __half* A, const __half* B, int K,
                                              float acc[4][8][4],
                                              int wm, int wn, int lane, int tid) {
    int nch = K / BK;
    issue_stage(sb,                A, B, 0,      K, tid);
    issue_stage(sb + ST_BYTES,     A, B, BK,     K, tid);
    issue_stage(sb + 2 * ST_BYTES, A, B, 2 * BK, K, tid);
    for (int c = 0; c < nch; c++) {
        int rem = nch - 1 - c;
        if (rem >= 2) cp_wait2(); else if (rem == 1) cp_wait1(); else cp_wait0();
        __syncthreads();
        compute_stage(sb + (c & 3) * ST_BYTES, acc, wm, wn, lane);
        if (c + 3 < nch)
            issue_stage(sb + ((c + 3) & 3) * ST_BYTES, A, B, (c + 3) * BK, K, tid);
    }
}

// ---------------- router -----------------------------------------------------
// two-phase mean for parallelism (R4's 32-block version was latency-bound)
__global__ void mean1_kernel(const float* __restrict__ x) {
    int b = blockIdx.x >> 3, chunk = blockIdx.x & 7;
    const float* xb = x + (size_t)b * Nn * Dd + (size_t)chunk * 128 * Dd;
    for (int d = threadIdx.x; d < Dd; d += blockDim.x) {
        float s = 0.f;
        const float* p = xb + d;
        #pragma unroll 8
        for (int n = 0; n < 128; n++) s += p[(size_t)n * Dd];
        g_pmean[(b * 8 + chunk) * Dd + d] = s;
    }
}
__global__ void mean2_kernel() {
    int b = blockIdx.x;
    for (int d = threadIdx.x; d < Dd; d += blockDim.x) {
        float s = 0.f;
        #pragma unroll
        for (int c = 0; c < 8; c++) s += g_pmean[(b * 8 + c) * Dd + d];
        g_xmean[b * Dd + d] = s * (1.0f / Nn);
    }
}

__global__ void gate_kernel(const float* __restrict__ rw, float* __restrict__ aux_out) {
    __shared__ float s_probs[Bq][Ee];
    __shared__ int   s_top1[Bq];
    int warp = threadIdx.x >> 5, lane = threadIdx.x & 31;
    int nwarp = blockDim.x >> 5;
    for (int b = warp; b < Bq; b += nwarp) {
        float logits[Ee];
        #pragma unroll
        for (int e = 0; e < Ee; e++) {
            float s = 0.f;
            for (int d = lane; d < Dd; d += 32)
                s += g_xmean[b * Dd + d] * rw[e * Dd + d];
            #pragma unroll
            for (int o = 16; o; o >>= 1) s += __shfl_xor_sync(0xffffffffu, s, o);
            logits[e] = s;
        }
        if (lane == 0) {
            float mx = logits[0];
            #pragma unroll
            for (int e = 1; e < Ee; e++) mx = fmaxf(mx, logits[e]);
            float p[Ee], se = 0.f;
            #pragma unroll
            for (int e = 0; e < Ee; e++) { p[e] = expf(logits[e] - mx); se += p[e]; }
            float inv = 1.0f / se;
            #pragma unroll
            for (int e = 0; e < Ee; e++) p[e] *= inv;
            int i0 = 0;
            #pragma unroll
            for (int e = 1; e < Ee; e++) if (p[e] > p[i0]) i0 = e;
            int i1 = (i0 == 0) ? 1 : 0;
            #pragma unroll
            for (int e = 0; e < Ee; e++) if (e != i1 && e != i0 && p[e] > p[i1]) i1 = e;
            float ws = p[i0] + p[i1];
            #pragma unroll
            for (int e = 0; e < Ee; e++) { g_combine[b * Ee + e] = 0.f; g_slot[b * Ee + e] = -1; }
            g_combine[b * Ee + i0] = p[i0] / ws;  g_slot[b * Ee + i0] = b * 2;
            g_combine[b * Ee + i1] = p[i1] / ws;  g_slot[b * Ee + i1] = b * 2 + 1;
            #pragma unroll
            for (int e = 0; e < Ee; e++) s_probs[b][e] = p[e];
            s_top1[b] = i0;
        }
    }
    __syncthreads();
    if (threadIdx.x == 0 && aux_out != nullptr) {
        float aux = 0.f;
        for (int e = 0; e < Ee; e++) {
            float pm = 0.f; int c = 0;
            for (int b = 0; b < Bq; b++) { pm += s_probs[b][e]; c += (s_top1[b] == e); }
            aux += (pm / Bq) * ((float)c / Bq);
        }
        aux_out[0] = (float)Ee * aux;
    }
}

// ---------------- conversions ------------------------------------------------
// weights fp32 -> fp16, streaming stores
__global__ void cvt_kernel(const float* __restrict__ in, __half* __restrict__ out, int n4) {
    int i = blockIdx.x * blockDim.x + threadIdx.x;
    if (i >= n4) return;
    float4 v = ((const float4*)in)[i];
    __half2 h0 = __floats2half2_rn(v.x, v.y);
    __half2 h1 = __floats2half2_rn(v.z, v.w);
    stcs_v2u32((char*)out + 8 * (size_t)i,
               *reinterpret_cast<uint32_t*>(&h0), *reinterpret_cast<uint32_t*>(&h1));
}

// fused: x -> xc (straight) + xt (transposed), reads x once
__global__ void xcvt_kernel(const float* __restrict__ x) {
    __shared__ float t[32][33];
    int b = blockIdx.z;
    int d0 = blockIdx.x * 32, n0 = blockIdx.y * 32;
    int tx = threadIdx.x, ty = threadIdx.y;
    const float* xb = x + (size_t)b * Nn * Dd;
    size_t cbase = (size_t)b * Nn * Dd;
    #pragma unroll
    for (int k = 0; k < 32; k += 8) {
        float v = xb[(size_t)(n0 + ty + k) * Dd + d0 + tx];
        t[ty + k][tx] = v;
        stcs_u16(g_xc + cbase + (size_t)(n0 + ty + k) * Dd + d0 + tx, __float2half_rn(v));
    }
    __syncthreads();
    size_t base = (size_t)b * Dd * Nn;
    #pragma unroll
    for (int k = 0; k < 32; k += 8)
        stcs_u16(g_xt + base + (size_t)(d0 + ty + k) * Nn + n0 + tx,
                 __float2half_rn(t[tx][ty + k]));
}

// ---------------- GEMM1 (merged token+channel launch) ------------------------
__global__ void __launch_bounds__(256, 1) gemm1_mma(const float* __restrict__ tok_b1,
                                                    const float* __restrict__ ch_b1) {
    extern __shared__ char smem[];
    int b = blockIdx.z, eg = blockIdx.y;
    int is_token = (eg < E_TOK);
    int el = is_token ? eg : (eg - E_TOK);
    float w = g_combine[b * Ee + eg];
    if (w == 0.f) return;
    int slot = g_slot[b * Ee + eg];
    int Nh = is_token ? HN : HD;
    int K  = is_token ? Nn : Dd;
    int tilesN = Nh / BN;
    int m0 = (blockIdx.x / tilesN) * BM;
    int n0 = (blockIdx.x % tilesN) * BN;

    const __half *A, *B;
    if (is_token) {
        A = g_xt  + (size_t)b  * Dd * Nn + (size_t)m0 * Nn;
        B = g_w1t + (size_t)el * HN * Nn + (size_t)n0 * Nn;
    } else {
        A = g_xc  + (size_t)b  * Nn * Dd + (size_t)m0 * Dd;
        B = g_w1c + (size_t)el * HD * Dd + (size_t)n0 * Dd;
    }

    uint32_t sb = s2u(smem);
    int tid = threadIdx.x, wid = tid >> 5, lane = tid & 31;
    int wm = wid >> 2, wn = wid & 3;

    float acc[4][8][4] = {};
    gemm_pipeline(sb, A, B, K, acc, wm, wn, lane, tid);

    __half* H = g_hid + (size_t)slot * SLOT_STRIDE;
    const float* b1e = (is_token ? tok_b1 : ch_b1) + el * Nh;
    #pragma unroll
    for (int mf = 0; mf < 4; mf++) {
        int m = m0 + wm * 64 + mf * 16 + (lane >> 2);
        #pragma unroll
        for (int nf = 0; nf < 8; nf++) {
            int col = n0 + wn * 64 + nf * 8 + (lane & 3) * 2;
            float bv0 = b1e[col], bv1 = b1e[col + 1];
            #pragma unroll
            for (int half = 0; half < 2; half++) {
                int mm = m + half * 8;
                float v0 = w * gelu_tanh(acc[mf][nf][half * 2]     + bv0);
                float v1 = w * gelu_tanh(acc[mf][nf][half * 2 + 1] + bv1);
                __half2 hh = __floats2half2_rn(v0, v1);
                stcs_u32(H + (size_t)mm * Nh + col, *reinterpret_cast<uint32_t*>(&hh));
            }
        }
    }
}

// ---------------- GEMM2 (phase-split: rank0 writes, rank1 accumulates) -------
__global__ void __launch_bounds__(256, 1) gemm2_mma(const float* __restrict__ tok_b2,
                                                    const float* __restrict__ ch_b2,
                                                    float* __restrict__ out, int phase) {
    extern __shared__ char smem[];
    // phase0 reversed-b (catch gemm1's freshest hid); phase1 forward-b (catch
    // phase0's freshest out lines).
    int b = phase ? blockIdx.z : (Bq - 1 - blockIdx.z);
    int n0 = (blockIdx.x / (Dd / BN)) * BM;
    int d0 = (blockIdx.x % (Dd / BN)) * BN;

    int ae[2]; float aw[2]; int cnt = 0;
    #pragma unroll
    for (int e = 0; e < Ee; e++) {
        float wv = g_combine[b * Ee + e];
        if (wv != 0.f && cnt < 2) { ae[cnt] = e; aw[cnt] = wv; cnt++; }
    }
    if (phase >= cnt) return;
    int e = ae[phase];
    float w = aw[phase];
    int slot = g_slot[b * Ee + e];

    const __half *A, *B;
    int K;
    if (e < E_TOK) {
        A = g_w2t + (size_t)e * Nn * HN + (size_t)n0 * HN;
        B = g_hid + (size_t)slot * SLOT_STRIDE + (size_t)d0 * HN;
        K = HN;
    } else {
        A = g_hid + (size_t)slot * SLOT_STRIDE + (size_t)n0 * HD;
        B = g_w2c + (size_t)(e - E_TOK) * Dd * HD + (size_t)d0 * HD;
        K = HD;
    }

    uint32_t sb = s2u(smem);
    int tid = threadIdx.x, wid = tid >> 5, lane = tid & 31;
    int wm = wid >> 2, wn = wid & 3;

    float acc[4][8][4] = {};
    gemm_pipeline(sb, A, B, K, acc, wm, wn, lane, tid);

    #pragma unroll
    for (int mf = 0; mf < 4; mf++) {
        int m = n0 + wm * 64 + mf * 16 + (lane >> 2);
        #pragma unroll
        for (int half = 0; half < 2; half++) {
            int mm = m + half * 8;
            float rowb = (e < E_TOK) ? w * tok_b2[e * Nn + mm] : 0.f;
            float* orow = out + ((size_t)b * Nn + mm) * Dd;
            #pragma unroll
            for (int nf = 0; nf < 8; nf++) {
                int col = d0 + wn * 64 + nf * 8 + (lane & 3) * 2;
                float cb0 = 0.f, cb1 = 0.f;
                if (e >= E_TOK) {
                    const float* cb = ch_b2 + (e - E_TOK) * Dd;
                    cb0 = w * cb[col];
                    cb1 = w * cb[col + 1];
                }
                float v0 = acc[mf][nf][half * 2]     + rowb + cb0;
                float v1 = acc[mf][nf][half * 2 + 1] + rowb + cb1;
                if (phase) {
                    float2 prev = *(const float2*)(orow + col);
                    v0 += prev.x; v1 += prev.y;
                }
                stcs_v2f32(orow + col, v0, v1);
            }
        }
    }
}

// ---------------- launch -----------------------------------------------------
extern "C" void kernel_launch(void* const* d_in, const int* in_sizes, int n_in,
                              void* d_out, int out_size) {
    const float* x      = (const float*)d_in[0];
    const float* rw     = (const float*)d_in[1];
    const float* tok_w1 = (const float*)d_in[2];
    const float* tok_b1 = (const float*)d_in[3];
    const float* tok_w2 = (const float*)d_in[4];
    const float* tok_b2 = (const float*)d_in[5];
    const float* ch_w1  = (const float*)d_in[6];
    const float* ch_b1  = (const float*)d_in[7];
    const float* ch_w2  = (const float*)d_in[8];
    const float* ch_b2  = (const float*)d_in[9];
    float* out = (float*)d_out;
    (void)in_sizes; (void)n_in;
    float* auxp = (out_size > Bq * Nn * Dd) ? (out + (size_t)Bq * Nn * Dd) : nullptr;

    cudaFuncSetAttribute(gemm1_mma, cudaFuncAttributeMaxDynamicSharedMemorySize, SMEM_DYN);
    cudaFuncSetAttribute(gemm2_mma, cudaFuncAttributeMaxDynamicSharedMemorySize, SMEM_DYN);

    mean1_kernel<<<Bq * 8, 256>>>(x);
    mean2_kernel<<<Bq, 256>>>();
    gate_kernel<<<1, 256>>>(rw, auxp);

    {
        __half *p_w1t, *p_w2t, *p_w1c, *p_w2c;
        cudaGetSymbolAddress((void**)&p_w1t, g_w1t);
        cudaGetSymbolAddress((void**)&p_w2t, g_w2t);
        cudaGetSymbolAddress((void**)&p_w1c, g_w1c);
        cudaGetSymbolAddress((void**)&p_w2c, g_w2c);

        xcvt_kernel<<<dim3(Dd / 32, Nn / 32, Bq), dim3(32, 8)>>>(x);
        int n4a = E_TOK * HN * Nn / 4;
        cvt_kernel<<<(n4a + 255) / 256, 256>>>(tok_w1, p_w1t, n4a);
        cvt_kernel<<<(n4a + 255) / 256, 256>>>(tok_w2, p_w2t, n4a);
        int n4c = E_CH * HD * Dd / 4;
        cvt_kernel<<<(n4c + 255) / 256, 256>>>(ch_w1, p_w1c, n4c);
        cvt_kernel<<<(n4c + 255) / 256, 256>>>(ch_w2, p_w2c, n4c);
    }

    // merged GEMM1: token (y=0..3, 6x16 tiles) + channel (y=4..7, 8x12 tiles)
    dim3 g1(96, Ee, Bq);
    gemm1_mma<<<g1, 256, SMEM_DYN>>>(tok_b1, ch_b1);

    // GEMM2 phase-split
    dim3 g2((Nn / BM) * (Dd / BN), 1, Bq);   // 24 x 1 x 32
    gemm2_mma<<<g2, 256, SMEM_DYN>>>(tok_b2, ch_b2, out, 0);
    gemm2_mma<<<g2, 256, SMEM_DYN>>>(tok_b2, ch_b2, out, 1);
}

// round 7
// speedup vs baseline: 7.7671x; 1.0668x over previous
#include <cuda_runtime.h>
#include <cuda_fp16.h>
#include <math.h>
#include <stdint.h>

#define Bq    32
#define Nn    1024
#define Dd    768
#define E_TOK 4
#define E_CH  4
#define Ee    8
#define HN    4096
#define HD    3072

#define SLOT_STRIDE 3145728   // 768*4096 == 1024*3072

// ---------------- scratch (__device__ globals: sanctioned scratch path) -----
__device__ float g_pmean[Bq * 8 * Dd];
__device__ float g_xmean[Bq * Dd];
__device__ float g_combine[Bq * Ee];
__device__ int   g_slot[Bq * Ee];
__device__ int   g_wl[Bq * 2];          // compact work list: (b<<8)|eg, 64 entries

__device__ __half g_xt [(size_t)Bq * Dd * Nn];
__device__ __half g_xc [(size_t)Bq * Nn * Dd];
__device__ __half g_w1t[(size_t)E_TOK * HN * Nn];
__device__ __half g_w2t[(size_t)E_TOK * Nn * HN];
__device__ __half g_w1c[(size_t)E_CH * HD * Dd];
__device__ __half g_w2c[(size_t)E_CH * Dd * HD];
__device__ __half g_hid[(size_t)Bq * 2 * SLOT_STRIDE];

// ---------------- smem geometry ---------------------------------------------
// CTA tile 128x128x64 fp16, 3 stages -> 108KB smem -> 2 CTAs/SM for latency hiding.
#define BM 128
#define BN 128
#define BK 64
#define SKB 144
#define A_BYTES (BM * SKB)             // 18432
#define B_BYTES (BN * SKB)             // 18432
#define ST_BYTES (A_BYTES + B_BYTES)   // 36864
#define NSTAGE 3
#define SMEM_DYN (NSTAGE * ST_BYTES)   // 110592

// ---------------- PTX helpers ------------------------------------------------
__device__ __forceinline__ uint32_t s2u(const void* p) {
    uint32_t a;
    asm("{ .reg .u64 t; cvta.to.shared.u64 t, %1; cvt.u32.u64 %0, t; }" : "=r"(a) : "l"(p));
    return a;
}
__device__ __forceinline__ void cp16(uint32_t sdst, const void* g) {
    asm volatile("cp.async.cg.shared.global [%0], [%1], 16;" :: "r"(sdst), "l"(g));
}
__device__ __forceinline__ void cp_commit() { asm volatile("cp.async.commit_group;" ::: "memory"); }
__device__ __forceinline__ void cp_wait1() { asm volatile("cp.async.wait_group 1;" ::: "memory"); }
__device__ __forceinline__ void cp_wait0() { asm volatile("cp.async.wait_group 0;" ::: "memory"); }
__device__ __forceinline__ void ldsm4(uint32_t* r, uint32_t addr) {
    asm volatile("ldmatrix.sync.aligned.m8n8.x4.shared.b16 {%0,%1,%2,%3}, [%4];"
                 : "=r"(r[0]), "=r"(r[1]), "=r"(r[2]), "=r"(r[3]) : "r"(addr));
}
__device__ __forceinline__ void mma_f16(float* c, const uint32_t* a, const uint32_t* b) {
    asm volatile(
        "mma.sync.aligned.m16n8k16.row.col.f32.f16.f16.f32 "
        "{%0,%1,%2,%3}, {%4,%5,%6,%7}, {%8,%9}, {%0,%1,%2,%3};"
        : "+f"(c[0]), "+f"(c[1]), "+f"(c[2]), "+f"(c[3])
        : "r"(a[0]), "r"(a[1]), "r"(a[2]), "r"(a[3]), "r"(b[0]), "r"(b[1]));
}
__device__ __forceinline__ void stcs_u16(__half* p, __half v) {
    unsigned short u = *reinterpret_cast<unsigned short*>(&v);
    asm volatile("st.global.cs.u16 [%0], %1;" :: "l"(p), "h"(u) : "memory");
}
__device__ __forceinline__ void stcs_u32(void* p, uint32_t v) {
    asm volatile("st.global.cs.u32 [%0], %1;" :: "l"(p), "r"(v) : "memory");
}
__device__ __forceinline__ void stcs_v2u32(void* p, uint32_t a, uint32_t b) {
    asm volatile("st.global.cs.v2.u32 [%0], {%1, %2};" :: "l"(p), "r"(a), "r"(b) : "memory");
}
__device__ __forceinline__ void stcs_v2f32(void* p, float a, float b) {
    asm volatile("st.global.cs.v2.f32 [%0], {%1, %2};" :: "l"(p), "f"(a), "f"(b) : "memory");
}
__device__ __forceinline__ float gelu_tanh(float v) {
    float c = 0.7978845608028654f * (v + 0.044715f * v * v * v);
    return 0.5f * v * (1.0f + tanhf(c));
}

// ---------------- GEMM core --------------------------------------------------
template <int R>
__device__ __forceinline__ void cpa_tile(uint32_t sdst, const __half* __restrict__ g,
                                         int k0, int strideK, int tid) {
    #pragma unroll
    for (int i = 0; i < R * 8 / 256; i++) {
        int c = tid + i * 256;
        int row = c >> 3, seg = c & 7;
        cp16(sdst + row * SKB + seg * 16,
             g + (size_t)row * strideK + k0 + seg * 8);
    }
}

__device__ __forceinline__ void issue_stage(uint32_t sbase,
                                            const __half* A, const __half* B,
                                            int k0, int strideK, int tid) {
    cpa_tile<BM>(sbase, A, k0, strideK, tid);
    cpa_tile<BN>(sbase + A_BYTES, B, k0, strideK, tid);
    cp_commit();
}

// warp layout: 2x4 (wm in 0..1, wn in 0..3), warp tile 64(M) x 32(N)
__device__ __forceinline__ void compute_stage(uint32_t s, float acc[4][4][4],
                                              int wm, int wn, int lane) {
    uint32_t aRow = lane & 15;
    uint32_t aK   = (lane >> 4) * 8;
    uint32_t bRow = (lane & 7) + ((lane >> 4) & 1) * 8;
    uint32_t bK   = ((lane >> 3) & 1) * 8;
    uint32_t sA = s, sB = s + A_BYTES;
    #pragma unroll
    for (int ks = 0; ks < 4; ks++) {
        uint32_t b[4][2];
        #pragma unroll
        for (int q = 0; q < 2; q++) {
            uint32_t t[4];
            ldsm4(t, sB + (wn * 32 + q * 16 + bRow) * SKB + (ks * 16 + bK) * 2);
            b[q * 2][0] = t[0]; b[q * 2][1] = t[1];
            b[q * 2 + 1][0] = t[2]; b[q * 2 + 1][1] = t[3];
        }
        #pragma unroll
        for (int mf = 0; mf < 4; mf++) {
            uint32_t a[4];
            ldsm4(a, sA + (wm * 64 + mf * 16 + aRow) * SKB + (ks * 16 + aK) * 2);
            #pragma unroll
            for (int nf = 0; nf < 4; nf++)
                mma_f16(acc[mf][nf], a, b[nf]);
        }
    }
}

__device__ __forceinline__ void gemm_pipeline(uint32_t sb,
                                              const __half* A, const __half* B, int K,
                                              float acc[4][4][4],
                                              int wm, int wn, int lane, int tid) {
    int nch = K / BK;
    issue_stage(sb,            A, B, 0,  K, tid);
    issue_stage(sb + ST_BYTES, A, B, BK, K, tid);
    for (int c = 0; c < nch; c++) {
        if (c + 1 < nch) cp_wait1(); else cp_wait0();
        __syncthreads();
        compute_stage(sb + (c % 3) * ST_BYTES, acc, wm, wn, lane);
        if (c + 2 < nch)
            issue_stage(sb + ((c + 2) % 3) * ST_BYTES, A, B, (c + 2) * BK, K, tid);
    }
    __syncthreads();   // make back-to-back pipeline calls safe (nch % 3 != 0)
}

// ---------------- router -----------------------------------------------------
__global__ void mean1_kernel(const float* __restrict__ x) {
    int b = blockIdx.x >> 3, chunk = blockIdx.x & 7;
    const float* xb = x + (size_t)b * Nn * Dd + (size_t)chunk * 128 * Dd;
    for (int d = threadIdx.x; d < Dd; d += blockDim.x) {
        float s = 0.f;
        const float* p = xb + d;
        #pragma unroll 8
        for (int n = 0; n < 128; n++) s += p[(size_t)n * Dd];
        g_pmean[(b * 8 + chunk) * Dd + d] = s;
    }
}
__global__ void mean2_kernel() {
    int b = blockIdx.x;
    for (int d = threadIdx.x; d < Dd; d += blockDim.x) {
        float s = 0.f;
        #pragma unroll
        for (int c = 0; c < 8; c++) s += g_pmean[(b * 8 + c) * Dd + d];
        g_xmean[b * Dd + d] = s * (1.0f / Nn);
    }
}

__global__ void gate_kernel(const float* __restrict__ rw, float* __restrict__ aux_out) {
    __shared__ float s_probs[Bq][Ee];
    __shared__ int   s_top1[Bq];
    __shared__ int   s_top2[Bq];
    int warp = threadIdx.x >> 5, lane = threadIdx.x & 31;
    int nwarp = blockDim.x >> 5;
    for (int b = warp; b < Bq; b += nwarp) {
        float logits[Ee];
        #pragma unroll
        for (int e = 0; e < Ee; e++) {
            float s = 0.f;
            for (int d = lane; d < Dd; d += 32)
                s += g_xmean[b * Dd + d] * rw[e * Dd + d];
            #pragma unroll
            for (int o = 16; o; o >>= 1) s += __shfl_xor_sync(0xffffffffu, s, o);
            logits[e] = s;
        }
        if (lane == 0) {
            float mx = logits[0];
            #pragma unroll
            for (int e = 1; e < Ee; e++) mx = fmaxf(mx, logits[e]);
            float p[Ee], se = 0.f;
            #pragma unroll
            for (int e = 0; e < Ee; e++) { p[e] = expf(logits[e] - mx); se += p[e]; }
            float inv = 1.0f / se;
            #pragma unroll
            for (int e = 0; e < Ee; e++) p[e] *= inv;
            int i0 = 0;
            #pragma unroll
            for (int e = 1; e < Ee; e++) if (p[e] > p[i0]) i0 = e;
            int i1 = (i0 == 0) ? 1 : 0;
            #pragma unroll
            for (int e = 0; e < Ee; e++) if (e != i1 && e != i0 && p[e] > p[i1]) i1 = e;
            float ws = p[i0] + p[i1];
            #pragma unroll
            for (int e = 0; e < Ee; e++) { g_combine[b * Ee + e] = 0.f; g_slot[b * Ee + e] = -1; }
            g_combine[b * Ee + i0] = p[i0] / ws;  g_slot[b * Ee + i0] = b * 2;
            g_combine[b * Ee + i1] = p[i1] / ws;  g_slot[b * Ee + i1] = b * 2 + 1;
            #pragma unroll
            for (int e = 0; e < Ee; e++) s_probs[b][e] = p[e];
            s_top1[b] = i0;
            s_top2[b] = i1;
        }
    }
    __syncthreads();
    if (threadIdx.x == 0) {
        // compact work list in fixed (b, e) order -> deterministic
        int cnt = 0;
        for (int b = 0; b < Bq; b++)
            for (int e = 0; e < Ee; e++)
                if (e == s_top1[b] || e == s_top2[b]) g_wl[cnt++] = (b << 8) | e;
        if (aux_out != nullptr) {
            float aux = 0.f;
            for (int e = 0; e < Ee; e++) {
                float pm = 0.f; int c = 0;
                for (int b = 0; b < Bq; b++) { pm += s_probs[b][e]; c += (s_top1[b] == e); }
                aux += (pm / Bq) * ((float)c / Bq);
            }
            aux_out[0] = (float)Ee * aux;
        }
    }
}

// ---------------- conversions ------------------------------------------------
__global__ void cvt_kernel(const float* __restrict__ in, __half* __restrict__ out, int n4) {
    int i = blockIdx.x * blockDim.x + threadIdx.x;
    if (i >= n4) return;
    float4 v = ((const float4*)in)[i];
    __half2 h0 = __floats2half2_rn(v.x, v.y);
    __half2 h1 = __floats2half2_rn(v.z, v.w);
    stcs_v2u32((char*)out + 8 * (size_t)i,
               *reinterpret_cast<uint32_t*>(&h0), *reinterpret_cast<uint32_t*>(&h1));
}

__global__ void xcvt_kernel(const float* __restrict__ x) {
    __shared__ float t[32][33];
    int b = blockIdx.z;
    int d0 = blockIdx.x * 32, n0 = blockIdx.y * 32;
    int tx = threadIdx.x, ty = threadIdx.y;
    const float* xb = x + (size_t)b * Nn * Dd;
    size_t cbase = (size_t)b * Nn * Dd;
    #pragma unroll
    for (int k = 0; k < 32; k += 8) {
        float v = xb[(size_t)(n0 + ty + k) * Dd + d0 + tx];
        t[ty + k][tx] = v;
        stcs_u16(g_xc + cbase + (size_t)(n0 + ty + k) * Dd + d0 + tx, __float2half_rn(v));
    }
    __syncthreads();
    size_t base = (size_t)b * Dd * Nn;
    #pragma unroll
    for (int k = 0; k < 32; k += 8)
        stcs_u16(g_xt + base + (size_t)(d0 + ty + k) * Nn + n0 + tx,
                 __float2half_rn(t[tx][ty + k]));
}

// ---------------- GEMM1 (work-list driven, 2 CTA/SM) -------------------------
__global__ void __launch_bounds__(256, 2) gemm1_mma(const float* __restrict__ tok_b1,
                                                    const float* __restrict__ ch_b1) {
    extern __shared__ char smem[];
    int code = g_wl[blockIdx.y];
    int b = code >> 8, eg = code & 255;
    int is_token = (eg < E_TOK);
    int el = is_token ? eg : (eg - E_TOK);
    float w = g_combine[b * Ee + eg];
    int slot = g_slot[b * Ee + eg];
    int Nh = is_token ? HN : HD;
    int K  = is_token ? Nn : Dd;
    int tilesN = Nh / BN;                  // 32 (token) or 24 (channel)
    int m0 = (blockIdx.x / tilesN) * BM;   // both families: 192 tiles total
    int n0 = (blockIdx.x % tilesN) * BN;

    const __half *A, *B;
    if (is_token) {
        A = g_xt  + (size_t)b  * Dd * Nn + (size_t)m0 * Nn;
        B = g_w1t + (size_t)el * HN * Nn + (size_t)n0 * Nn;
    } else {
        A = g_xc  + (size_t)b  * Nn * Dd + (size_t)m0 * Dd;
        B = g_w1c + (size_t)el * HD * Dd + (size_t)n0 * Dd;
    }

    uint32_t sb = s2u(smem);
    int tid = threadIdx.x, wid = tid >> 5, lane = tid & 31;
    int wm = wid >> 2, wn = wid & 3;

    float acc[4][4][4] = {};
    gemm_pipeline(sb, A, B, K, acc, wm, wn, lane, tid);

    __half* H = g_hid + (size_t)slot * SLOT_STRIDE;
    const float* b1e = (is_token ? tok_b1 : ch_b1) + el * Nh;
    #pragma unroll
    for (int mf = 0; mf < 4; mf++) {
        int m = m0 + wm * 64 + mf * 16 + (lane >> 2);
        #pragma unroll
        for (int nf = 0; nf < 4; nf++) {
            int col = n0 + wn * 32 + nf * 8 + (lane & 3) * 2;
            float bv0 = b1e[col], bv1 = b1e[col + 1];
            #pragma unroll
            for (int half = 0; half < 2; half++) {
                int mm = m + half * 8;
                float v0 = w * gelu_tanh(acc[mf][nf][half * 2]     + bv0);
                float v1 = w * gelu_tanh(acc[mf][nf][half * 2 + 1] + bv1);
                __half2 hh = __floats2half2_rn(v0, v1);
                stcs_u32(H + (size_t)mm * Nh + col, *reinterpret_cast<uint32_t*>(&hh));
            }
        }
    }
}

// ---------------- GEMM2 (phase-split, 2 CTA/SM) ------------------------------
__global__ void __launch_bounds__(256, 2) gemm2_mma(const float* __restrict__ tok_b2,
                                                    const float* __restrict__ ch_b2,
                                                    float* __restrict__ out, int phase) {
    extern __shared__ char smem[];
    int b = phase ? blockIdx.z : (Bq - 1 - blockIdx.z);
    int n0 = (blockIdx.x / (Dd / BN)) * BM;
    int d0 = (blockIdx.x % (Dd / BN)) * BN;

    int ae[2]; float aw[2]; int cnt = 0;
    #pragma unroll
    for (int e = 0; e < Ee; e++) {
        float wv = g_combine[b * Ee + e];
        if (wv != 0.f && cnt < 2) { ae[cnt] = e; aw[cnt] = wv; cnt++; }
    }
    if (phase >= cnt) return;
    int e = ae[phase];
    float w = aw[phase];
    int slot = g_slot[b * Ee + e];

    const __half *A, *B;
    int K;
    if (e < E_TOK) {
        A = g_w2t + (size_t)e * Nn * HN + (size_t)n0 * HN;
        B = g_hid + (size_t)slot * SLOT_STRIDE + (size_t)d0 * HN;
        K = HN;
    } else {
        A = g_hid + (size_t)slot * SLOT_STRIDE + (size_t)n0 * HD;
        B = g_w2c + (size_t)(e - E_TOK) * Dd * HD + (size_t)d0 * HD;
        K = HD;
    }

    uint32_t sb = s2u(smem);
    int tid = threadIdx.x, wid = tid >> 5, lane = tid & 31;
    int wm = wid >> 2, wn = wid & 3;

    float acc[4][4][4] = {};
    gemm_pipeline(sb, A, B, K, acc, wm, wn, lane, tid);

    #pragma unroll
    for (int mf = 0; mf < 4; mf++) {
        int m = n0 + wm * 64 + mf * 16 + (lane >> 2);
        #pragma unroll
        for (int half = 0; half < 2; half++) {
            int mm = m + half * 8;
            float rowb = (e < E_TOK) ? w * tok_b2[e * Nn + mm] : 0.f;
            float* orow = out + ((size_t)b * Nn + mm) * Dd;
            #pragma unroll
            for (int nf = 0; nf < 4; nf++) {
                int col = d0 + wn * 32 + nf * 8 + (lane & 3) * 2;
                float cb0 = 0.f, cb1 = 0.f;
                if (e >= E_TOK) {
                    const float* cb = ch_b2 + (e - E_TOK) * Dd;
                    cb0 = w * cb[col];
                    cb1 = w * cb[col + 1];
                }
                float v0 = acc[mf][nf][half * 2]     + rowb + cb0;
                float v1 = acc[mf][nf][half * 2 + 1] + rowb + cb1;
                if (phase) {
                    float2 prev = *(const float2*)(orow + col);
                    v0 += prev.x; v1 += prev.y;
                }
                stcs_v2f32(orow + col, v0, v1);
            }
        }
    }
}

// ---------------- launch -----------------------------------------------------
extern "C" void kernel_launch(void* const* d_in, const int* in_sizes, int n_in,
                              void* d_out, int out_size) {
    const float* x      = (const float*)d_in[0];
    const float* rw     = (const float*)d_in[1];
    const float* tok_w1 = (const float*)d_in[2];
    const float* tok_b1 = (const float*)d_in[3];
    const float* tok_w2 = (const float*)d_in[4];
    const float* tok_b2 = (const float*)d_in[5];
    const float* ch_w1  = (const float*)d_in[6];
    const float* ch_b1  = (const float*)d_in[7];
    const float* ch_w2  = (const float*)d_in[8];
    const float* ch_b2  = (const float*)d_in[9];
    float* out = (float*)d_out;
    (void)in_sizes; (void)n_in;
    float* auxp = (out_size > Bq * Nn * Dd) ? (out + (size_t)Bq * Nn * Dd) : nullptr;

    cudaFuncSetAttribute(gemm1_mma, cudaFuncAttributeMaxDynamicSharedMemorySize, SMEM_DYN);
    cudaFuncSetAttribute(gemm2_mma, cudaFuncAttributeMaxDynamicSharedMemorySize, SMEM_DYN);

    mean1_kernel<<<Bq * 8, 256>>>(x);
    mean2_kernel<<<Bq, 256>>>();
    gate_kernel<<<1, 256>>>(rw, auxp);

    {
        __half *p_w1t, *p_w2t, *p_w1c, *p_w2c;
        cudaGetSymbolAddress((void**)&p_w1t, g_w1t);
        cudaGetSymbolAddress((void**)&p_w2t, g_w2t);
        cudaGetSymbolAddress((void**)&p_w1c, g_w1c);
        cudaGetSymbolAddress((void**)&p_w2c, g_w2c);

        xcvt_kernel<<<dim3(Dd / 32, Nn / 32, Bq), dim3(32, 8)>>>(x);
        int n4a = E_TOK * HN * Nn / 4;
        cvt_kernel<<<(n4a + 255) / 256, 256>>>(tok_w1, p_w1t, n4a);
        cvt_kernel<<<(n4a + 255) / 256, 256>>>(tok_w2, p_w2t, n4a);
        int n4c = E_CH * HD * Dd / 4;
        cvt_kernel<<<(n4c + 255) / 256, 256>>>(ch_w1, p_w1c, n4c);
        cvt_kernel<<<(n4c + 255) / 256, 256>>>(ch_w2, p_w2c, n4c);
    }

    // GEMM1: exactly the 64 active (b, expert) pairs; 192 tiles each family
    dim3 g1(192, Bq * 2);
    gemm1_mma<<<g1, 256, SMEM_DYN>>>(tok_b1, ch_b1);

    // GEMM2 phase-split
    dim3 g2((Nn / BM) * (Dd / BN), 1, Bq);   // 48 x 1 x 32
    gemm2_mma<<<g2, 256, SMEM_DYN>>>(tok_b2, ch_b2, out, 0);
    gemm2_mma<<<g2, 256, SMEM_DYN>>>(tok_b2, ch_b2, out, 1);
}

// round 8
// speedup vs baseline: 7.8263x; 1.0076x over previous
#include <cuda_runtime.h>
#include <cuda_fp16.h>
#include <math.h>
#include <stdint.h>

#define Bq    32
#define Nn    1024
#define Dd    768
#define E_TOK 4
#define E_CH  4
#define Ee    8
#define HN    4096
#define HD    3072

#define SLOT_STRIDE 3145728   // 768*4096 == 1024*3072

// ---------------- scratch (__device__ globals: sanctioned scratch path) -----
__device__ float g_pmean[Bq * 8 * Dd];
__device__ float g_xmean[Bq * Dd];
__device__ float g_combine[Bq * Ee];
__device__ int   g_slot[Bq * Ee];
__device__ int   g_wl[Bq * 2];          // compact work list: (b<<8)|eg, 64 entries

__device__ __half g_xt [(size_t)Bq * Dd * Nn];
__device__ __half g_xc [(size_t)Bq * Nn * Dd];
__device__ __half g_w1t[(size_t)E_TOK * HN * Nn];
__device__ __half g_w2t[(size_t)E_TOK * Nn * HN];
__device__ __half g_w1c[(size_t)E_CH * HD * Dd];
__device__ __half g_w2c[(size_t)E_CH * Dd * HD];
__device__ __half g_hid[(size_t)Bq * 2 * SLOT_STRIDE];

// ---------------- smem geometry ---------------------------------------------
#define BM 128
#define BN 128
#define BK 64
#define SKB 144
#define A_BYTES (BM * SKB)             // 18432
#define B_BYTES (BN * SKB)             // 18432
#define ST_BYTES (A_BYTES + B_BYTES)   // 36864
#define NSTAGE 3
#define SMEM_DYN (NSTAGE * ST_BYTES)   // 110592

// ---------------- PTX helpers ------------------------------------------------
__device__ __forceinline__ uint32_t s2u(const void* p) {
    uint32_t a;
    asm("{ .reg .u64 t; cvta.to.shared.u64 t, %1; cvt.u32.u64 %0, t; }" : "=r"(a) : "l"(p));
    return a;
}
__device__ __forceinline__ void cp16(uint32_t sdst, const void* g) {
    asm volatile("cp.async.cg.shared.global [%0], [%1], 16;" :: "r"(sdst), "l"(g));
}
__device__ __forceinline__ void cp_commit() { asm volatile("cp.async.commit_group;" ::: "memory"); }
__device__ __forceinline__ void cp_wait1() { asm volatile("cp.async.wait_group 1;" ::: "memory"); }
__device__ __forceinline__ void cp_wait0() { asm volatile("cp.async.wait_group 0;" ::: "memory"); }
__device__ __forceinline__ void ldsm4(uint32_t* r, uint32_t addr) {
    asm volatile("ldmatrix.sync.aligned.m8n8.x4.shared.b16 {%0,%1,%2,%3}, [%4];"
                 : "=r"(r[0]), "=r"(r[1]), "=r"(r[2]), "=r"(r[3]) : "r"(addr));
}
__device__ __forceinline__ void mma_f16(float* c, const uint32_t* a, const uint32_t* b) {
    asm volatile(
        "mma.sync.aligned.m16n8k16.row.col.f32.f16.f16.f32 "
        "{%0,%1,%2,%3}, {%4,%5,%6,%7}, {%8,%9}, {%0,%1,%2,%3};"
        : "+f"(c[0]), "+f"(c[1]), "+f"(c[2]), "+f"(c[3])
        : "r"(a[0]), "r"(a[1]), "r"(a[2]), "r"(a[3]), "r"(b[0]), "r"(b[1]));
}
__device__ __forceinline__ void stcs_u16(__half* p, __half v) {
    unsigned short u = *reinterpret_cast<unsigned short*>(&v);
    asm volatile("st.global.cs.u16 [%0], %1;" :: "l"(p), "h"(u) : "memory");
}
__device__ __forceinline__ void stcs_u32(void* p, uint32_t v) {
    asm volatile("st.global.cs.u32 [%0], %1;" :: "l"(p), "r"(v) : "memory");
}
__device__ __forceinline__ void stcs_v2u32(void* p, uint32_t a, uint32_t b) {
    asm volatile("st.global.cs.v2.u32 [%0], {%1, %2};" :: "l"(p), "r"(a), "r"(b) : "memory");
}
__device__ __forceinline__ void stcs_v2f32(void* p, float a, float b) {
    asm volatile("st.global.cs.v2.f32 [%0], {%1, %2};" :: "l"(p), "f"(a), "f"(b) : "memory");
}
__device__ __forceinline__ float gelu_tanh(float v) {
    float c = 0.7978845608028654f * (v + 0.044715f * v * v * v);
    return 0.5f * v * (1.0f + tanhf(c));
}

// ---------------- GEMM core --------------------------------------------------
template <int R>
__device__ __forceinline__ void cpa_tile(uint32_t sdst, const __half* __restrict__ g,
                                         int k0, int strideK, int tid) {
    #pragma unroll
    for (int i = 0; i < R * 8 / 256; i++) {
        int c = tid + i * 256;
        int row = c >> 3, seg = c & 7;
        cp16(sdst + row * SKB + seg * 16,
             g + (size_t)row * strideK + k0 + seg * 8);
    }
}

__device__ __forceinline__ void issue_stage(uint32_t sbase,
                                            const __half* A, const __half* B,
                                            int k0, int strideK, int tid) {
    cpa_tile<BM>(sbase, A, k0, strideK, tid);
    cpa_tile<BN>(sbase + A_BYTES, B, k0, strideK, tid);
    cp_commit();
}

// warp layout: 2x4 (wm in 0..1, wn in 0..3), warp tile 64(M) x 32(N)
__device__ __forceinline__ void compute_stage(uint32_t s, float acc[4][4][4],
                                              int wm, int wn, int lane) {
    uint32_t aRow = lane & 15;
    uint32_t aK   = (lane >> 4) * 8;
    uint32_t bRow = (lane & 7) + ((lane >> 4) & 1) * 8;
    uint32_t bK   = ((lane >> 3) & 1) * 8;
    uint32_t sA = s, sB = s + A_BYTES;
    #pragma unroll
    for (int ks = 0; ks < 4; ks++) {
        uint32_t b[4][2];
        #pragma unroll
        for (int q = 0; q < 2; q++) {
            uint32_t t[4];
            ldsm4(t, sB + (wn * 32 + q * 16 + bRow) * SKB + (ks * 16 + bK) * 2);
            b[q * 2][0] = t[0]; b[q * 2][1] = t[1];
            b[q * 2 + 1][0] = t[2]; b[q * 2 + 1][1] = t[3];
        }
        #pragma unroll
        for (int mf = 0; mf < 4; mf++) {
            uint32_t a[4];
            ldsm4(a, sA + (wm * 64 + mf * 16 + aRow) * SKB + (ks * 16 + aK) * 2);
            #pragma unroll
            for (int nf = 0; nf < 4; nf++)
                mma_f16(acc[mf][nf], a, b[nf]);
        }
    }
}

__device__ __forceinline__ void gemm_pipeline(uint32_t sb,
                                              const __half* A, const __half* B, int K,
                                              float acc[4][4][4],
                                              int wm, int wn, int lane, int tid) {
    int nch = K / BK;
    issue_stage(sb,            A, B, 0,  K, tid);
    issue_stage(sb + ST_BYTES, A, B, BK, K, tid);
    for (int c = 0; c < nch; c++) {
        if (c + 1 < nch) cp_wait1(); else cp_wait0();
        __syncthreads();
        compute_stage(sb + (c % 3) * ST_BYTES, acc, wm, wn, lane);
        if (c + 2 < nch)
            issue_stage(sb + ((c + 2) % 3) * ST_BYTES, A, B, (c + 2) * BK, K, tid);
    }
    __syncthreads();   // back-to-back pipeline calls safe (nch % 3 != 0)
}

// ---------------- router -----------------------------------------------------
__global__ void mean1_kernel(const float* __restrict__ x) {
    int b = blockIdx.x >> 3, chunk = blockIdx.x & 7;
    const float* xb = x + (size_t)b * Nn * Dd + (size_t)chunk * 128 * Dd;
    for (int d = threadIdx.x; d < Dd; d += blockDim.x) {
        float s = 0.f;
        const float* p = xb + d;
        #pragma unroll 8
        for (int n = 0; n < 128; n++) s += p[(size_t)n * Dd];
        g_pmean[(b * 8 + chunk) * Dd + d] = s;
    }
}
__global__ void mean2_kernel() {
    int b = blockIdx.x;
    for (int d = threadIdx.x; d < Dd; d += blockDim.x) {
        float s = 0.f;
        #pragma unroll
        for (int c = 0; c < 8; c++) s += g_pmean[(b * 8 + c) * Dd + d];
        g_xmean[b * Dd + d] = s * (1.0f / Nn);
    }
}

__global__ void gate_kernel(const float* __restrict__ rw, float* __restrict__ aux_out) {
    __shared__ float s_probs[Bq][Ee];
    __shared__ int   s_top1[Bq];
    __shared__ int   s_top2[Bq];
    int warp = threadIdx.x >> 5, lane = threadIdx.x & 31;
    int nwarp = blockDim.x >> 5;
    for (int b = warp; b < Bq; b += nwarp) {
        float logits[Ee];
        #pragma unroll
        for (int e = 0; e < Ee; e++) {
            float s = 0.f;
            for (int d = lane; d < Dd; d += 32)
                s += g_xmean[b * Dd + d] * rw[e * Dd + d];
            #pragma unroll
            for (int o = 16; o; o >>= 1) s += __shfl_xor_sync(0xffffffffu, s, o);
            logits[e] = s;
        }
        if (lane == 0) {
            float mx = logits[0];
            #pragma unroll
            for (int e = 1; e < Ee; e++) mx = fmaxf(mx, logits[e]);
            float p[Ee], se = 0.f;
            #pragma unroll
            for (int e = 0; e < Ee; e++) { p[e] = expf(logits[e] - mx); se += p[e]; }
            float inv = 1.0f / se;
            #pragma unroll
            for (int e = 0; e < Ee; e++) p[e] *= inv;
            int i0 = 0;
            #pragma unroll
            for (int e = 1; e < Ee; e++) if (p[e] > p[i0]) i0 = e;
            int i1 = (i0 == 0) ? 1 : 0;
            #pragma unroll
            for (int e = 0; e < Ee; e++) if (e != i1 && e != i0 && p[e] > p[i1]) i1 = e;
            float ws = p[i0] + p[i1];
            #pragma unroll
            for (int e = 0; e < Ee; e++) { g_combine[b * Ee + e] = 0.f; g_slot[b * Ee + e] = -1; }
            g_combine[b * Ee + i0] = p[i0] / ws;  g_slot[b * Ee + i0] = b * 2;
            g_combine[b * Ee + i1] = p[i1] / ws;  g_slot[b * Ee + i1] = b * 2 + 1;
            #pragma unroll
            for (int e = 0; e < Ee; e++) s_probs[b][e] = p[e];
            s_top1[b] = i0;
            s_top2[b] = i1;
        }
    }
    __syncthreads();
    if (threadIdx.x == 0) {
        int cnt = 0;
        for (int b = 0; b < Bq; b++)
            for (int e = 0; e < Ee; e++)
                if (e == s_top1[b] || e == s_top2[b]) g_wl[cnt++] = (b << 8) | e;
        if (aux_out != nullptr) {
            float aux = 0.f;
            for (int e = 0; e < Ee; e++) {
                float pm = 0.f; int c = 0;
                for (int b = 0; b < Bq; b++) { pm += s_probs[b][e]; c += (s_top1[b] == e); }
                aux += (pm / Bq) * ((float)c / Bq);
            }
            aux_out[0] = (float)Ee * aux;
        }
    }
}

// ---------------- conversions ------------------------------------------------
// fused x -> xc + xt
__global__ void xcvt_kernel(const float* __restrict__ x) {
    __shared__ float t[32][33];
    int b = blockIdx.z;
    int d0 = blockIdx.x * 32, n0 = blockIdx.y * 32;
    int tx = threadIdx.x, ty = threadIdx.y;
    const float* xb = x + (size_t)b * Nn * Dd;
    size_t cbase = (size_t)b * Nn * Dd;
    #pragma unroll
    for (int k = 0; k < 32; k += 8) {
        float v = xb[(size_t)(n0 + ty + k) * Dd + d0 + tx];
        t[ty + k][tx] = v;
        stcs_u16(g_xc + cbase + (size_t)(n0 + ty + k) * Dd + d0 + tx, __float2half_rn(v));
    }
    __syncthreads();
    size_t base = (size_t)b * Dd * Nn;
    #pragma unroll
    for (int k = 0; k < 32; k += 8)
        stcs_u16(g_xt + base + (size_t)(d0 + ty + k) * Nn + n0 + tx,
                 __float2half_rn(t[tx][ty + k]));
}

// all four weight tensors in ONE kernel (also re-slots gemm1 into ncu -s 5)
#define N4_TW (E_TOK * HN * Nn / 4)          // 4194304
#define N4_CW (E_CH * HD * Dd / 4)           // 2359296
__global__ void cvt_all_kernel(const float* __restrict__ tok_w1, const float* __restrict__ tok_w2,
                               const float* __restrict__ ch_w1,  const float* __restrict__ ch_w2,
                               __half* __restrict__ o1, __half* __restrict__ o2,
                               __half* __restrict__ o3, __half* __restrict__ o4) {
    int i = blockIdx.x * blockDim.x + threadIdx.x;
    const float* in; __half* out; int idx;
    if (i < N4_TW)                    { in = tok_w1; out = o1; idx = i; }
    else if (i < 2 * N4_TW)           { in = tok_w2; out = o2; idx = i - N4_TW; }
    else if (i < 2 * N4_TW + N4_CW)   { in = ch_w1;  out = o3; idx = i - 2 * N4_TW; }
    else if (i < 2 * (N4_TW + N4_CW)) { in = ch_w2;  out = o4; idx = i - 2 * N4_TW - N4_CW; }
    else return;
    float4 v = ((const float4*)in)[idx];
    __half2 h0 = __floats2half2_rn(v.x, v.y);
    __half2 h1 = __floats2half2_rn(v.z, v.w);
    stcs_v2u32((char*)out + 8 * (size_t)idx,
               *reinterpret_cast<uint32_t*>(&h0), *reinterpret_cast<uint32_t*>(&h1));
}

// ---------------- GEMM1 (work-list driven, 2 CTA/SM) -------------------------
__global__ void __launch_bounds__(256, 2) gemm1_mma(const float* __restrict__ tok_b1,
                                                    const float* __restrict__ ch_b1) {
    extern __shared__ char smem[];
    int code = g_wl[blockIdx.y];
    int b = code >> 8, eg = code & 255;
    int is_token = (eg < E_TOK);
    int el = is_token ? eg : (eg - E_TOK);
    float w = g_combine[b * Ee + eg];
    int slot = g_slot[b * Ee + eg];
    int Nh = is_token ? HN : HD;
    int K  = is_token ? Nn : Dd;
    int tilesN = Nh / BN;
    int m0 = (blockIdx.x / tilesN) * BM;
    int n0 = (blockIdx.x % tilesN) * BN;

    const __half *A, *B;
    if (is_token) {
        A = g_xt  + (size_t)b  * Dd * Nn + (size_t)m0 * Nn;
        B = g_w1t + (size_t)el * HN * Nn + (size_t)n0 * Nn;
    } else {
        A = g_xc  + (size_t)b  * Nn * Dd + (size_t)m0 * Dd;
        B = g_w1c + (size_t)el * HD * Dd + (size_t)n0 * Dd;
    }

    uint32_t sb = s2u(smem);
    int tid = threadIdx.x, wid = tid >> 5, lane = tid & 31;
    int wm = wid >> 2, wn = wid & 3;

    float acc[4][4][4] = {};
    gemm_pipeline(sb, A, B, K, acc, wm, wn, lane, tid);

    __half* H = g_hid + (size_t)slot * SLOT_STRIDE;
    const float* b1e = (is_token ? tok_b1 : ch_b1) + el * Nh;
    #pragma unroll
    for (int mf = 0; mf < 4; mf++) {
        int m = m0 + wm * 64 + mf * 16 + (lane >> 2);
        #pragma unroll
        for (int nf = 0; nf < 4; nf++) {
            int col = n0 + wn * 32 + nf * 8 + (lane & 3) * 2;
            float bv0 = b1e[col], bv1 = b1e[col + 1];
            #pragma unroll
            for (int half = 0; half < 2; half++) {
                int mm = m + half * 8;
                float v0 = w * gelu_tanh(acc[mf][nf][half * 2]     + bv0);
                float v1 = w * gelu_tanh(acc[mf][nf][half * 2 + 1] + bv1);
                __half2 hh = __floats2half2_rn(v0, v1);
                stcs_u32(H + (size_t)mm * Nh + col, *reinterpret_cast<uint32_t*>(&hh));
            }
        }
    }
}

// ---------------- GEMM2 (merged experts, single launch, 2 CTA/SM) -----------
__global__ void __launch_bounds__(256, 2) gemm2_mma(const float* __restrict__ tok_b2,
                                                    const float* __restrict__ ch_b2,
                                                    float* __restrict__ out) {
    extern __shared__ char smem[];
    int b = Bq - 1 - blockIdx.z;   // reversed: catch gemm1's freshest hid in L2
    int n0 = (blockIdx.x / (Dd / BN)) * BM;
    int d0 = (blockIdx.x % (Dd / BN)) * BN;

    int ae[2]; float aw[2]; int cnt = 0;
    #pragma unroll
    for (int e = 0; e < Ee; e++) {
        float wv = g_combine[b * Ee + e];
        if (wv != 0.f && cnt < 2) { ae[cnt] = e; aw[cnt] = wv; cnt++; }
    }

    uint32_t sb = s2u(smem);
    int tid = threadIdx.x, wid = tid >> 5, lane = tid & 31;
    int wm = wid >> 2, wn = wid & 3;

    float acc[4][4][4] = {};
    for (int xi = 0; xi < cnt; xi++) {
        int e = ae[xi];
        int slot = g_slot[b * Ee + e];
        const __half *A, *B;
        int K;
        if (e < E_TOK) {
            A = g_w2t + (size_t)e * Nn * HN + (size_t)n0 * HN;
            B = g_hid + (size_t)slot * SLOT_STRIDE + (size_t)d0 * HN;
            K = HN;
        } else {
            A = g_hid + (size_t)slot * SLOT_STRIDE + (size_t)n0 * HD;
            B = g_w2c + (size_t)(e - E_TOK) * Dd * HD + (size_t)d0 * HD;
            K = HD;
        }
        gemm_pipeline(sb, A, B, K, acc, wm, wn, lane, tid);
    }

    #pragma unroll
    for (int mf = 0; mf < 4; mf++) {
        int m = n0 + wm * 64 + mf * 16 + (lane >> 2);
        #pragma unroll
        for (int half = 0; half < 2; half++) {
            int mm = m + half * 8;
            float rowb = 0.f;
            #pragma unroll
            for (int xi = 0; xi < 2; xi++)
                if (xi < cnt && ae[xi] < E_TOK) rowb += aw[xi] * tok_b2[ae[xi] * Nn + mm];
            float* orow = out + ((size_t)b * Nn + mm) * Dd;
            #pragma unroll
            for (int nf = 0; nf < 4; nf++) {
                int col = d0 + wn * 32 + nf * 8 + (lane & 3) * 2;
                float cb0 = 0.f, cb1 = 0.f;
                #pragma unroll
                for (int xi = 0; xi < 2; xi++)
                    if (xi < cnt && ae[xi] >= E_TOK) {
                        const float* cb = ch_b2 + (ae[xi] - E_TOK) * Dd;
                        cb0 += aw[xi] * cb[col];
                        cb1 += aw[xi] * cb[col + 1];
                    }
                stcs_v2f32(orow + col,
                           acc[mf][nf][half * 2]     + rowb + cb0,
                           acc[mf][nf][half * 2 + 1] + rowb + cb1);
            }
        }
    }
}

// ---------------- launch -----------------------------------------------------
extern "C" void kernel_launch(void* const* d_in, const int* in_sizes, int n_in,
                              void* d_out, int out_size) {
    const float* x      = (const float*)d_in[0];
    const float* rw     = (const float*)d_in[1];
    const float* tok_w1 = (const float*)d_in[2];
    const float* tok_b1 = (const float*)d_in[3];
    const float* tok_w2 = (const float*)d_in[4];
    const float* tok_b2 = (const float*)d_in[5];
    const float* ch_w1  = (const float*)d_in[6];
    const float* ch_b1  = (const float*)d_in[7];
    const float* ch_w2  = (const float*)d_in[8];
    const float* ch_b2  = (const float*)d_in[9];
    float* out = (float*)d_out;
    (void)in_sizes; (void)n_in;
    float* auxp = (out_size > Bq * Nn * Dd) ? (out + (size_t)Bq * Nn * Dd) : nullptr;

    cudaFuncSetAttribute(gemm1_mma, cudaFuncAttributeMaxDynamicSharedMemorySize, SMEM_DYN);
    cudaFuncSetAttribute(gemm2_mma, cudaFuncAttributeMaxDynamicSharedMemorySize, SMEM_DYN);

    // launches 1..5: router + conversions; launch 6 = gemm1 (ncu -s 5 -c 1 target)
    mean1_kernel<<<Bq * 8, 256>>>(x);
    mean2_kernel<<<Bq, 256>>>();
    gate_kernel<<<1, 256>>>(rw, auxp);
    xcvt_kernel<<<dim3(Dd / 32, Nn / 32, Bq), dim3(32, 8)>>>(x);

    {
        __half *p_w1t, *p_w2t, *p_w1c, *p_w2c;
        cudaGetSymbolAddress((void**)&p_w1t, g_w1t);
        cudaGetSymbolAddress((void**)&p_w2t, g_w2t);
        cudaGetSymbolAddress((void**)&p_w1c, g_w1c);
        cudaGetSymbolAddress((void**)&p_w2c, g_w2c);
        int n4 = 2 * (N4_TW + N4_CW);
        cvt_all_kernel<<<(n4 + 255) / 256, 256>>>(tok_w1, tok_w2, ch_w1, ch_w2,
                                                  p_w1t, p_w2t, p_w1c, p_w2c);
    }

    dim3 g1(192, Bq * 2);
    gemm1_mma<<<g1, 256, SMEM_DYN>>>(tok_b1, ch_b1);

    dim3 g2((Nn / BM) * (Dd / BN), 1, Bq);   // 48 x 1 x 32
    gemm2_mma<<<g2, 256, SMEM_DYN>>>(tok_b2, ch_b2, out);
}